// round 2
// baseline (speedup 1.0000x reference)
#include <cuda_runtime.h>
#include <cuda_bf16.h>
#include <math.h>

// ---------------- problem constants ----------------
#define BATCH 2
#define QLEN  16384
#define CH    256
#define HEADS 8
#define DHEAD 32
#define NV    13125          // 100*100 + 50*50 + 25*25
#define NOFF  192            // H*L*P*2
#define NATT  96             // H*L*P
#define FFN   1024
#define MQ    (BATCH*QLEN)   // 32768
#define MV    (BATCH*NV)     // 26250

// ---------------- scratch (allocation-free) ----------------
__device__ float g_q   [MQ*CH];     // ln1(query)+pos
__device__ float g_v   [MV*CH];     // value projection
__device__ float g_off [MQ*NOFF];   // sampling offsets
__device__ float g_attn[MQ*NATT];   // attention logits
__device__ float g_samp[MQ*CH];     // deformable attention output
__device__ float g_x   [MQ*CH];     // after out-proj residual
__device__ float g_h   [MQ*CH];     // ln2(x)
__device__ float g_hid [MQ*FFN];    // ffn hidden

// ---------------- helpers ----------------
__device__ __forceinline__ float gelu_f(float x) {
    return 0.5f * x * (1.0f + erff(x * 0.70710678118654752f));
}

// ---------------- LayerNorm (one 256-thread block per row, C=256) ----------------
__global__ void ln_kernel(const float* __restrict__ x,
                          const float* __restrict__ g,
                          const float* __restrict__ b,
                          const float* __restrict__ add,   // optional, may be null
                          float* __restrict__ out)
{
    int row = blockIdx.x;
    int t   = threadIdx.x;
    size_t base = (size_t)row * CH + t;
    float v = x[base];

    __shared__ float sh[CH];
    sh[t] = v; __syncthreads();
    #pragma unroll
    for (int s = 128; s > 0; s >>= 1) { if (t < s) sh[t] += sh[t + s]; __syncthreads(); }
    float mean = sh[0] * (1.0f / CH);
    __syncthreads();
    float d = v - mean;
    sh[t] = d * d; __syncthreads();
    #pragma unroll
    for (int s = 128; s > 0; s >>= 1) { if (t < s) sh[t] += sh[t + s]; __syncthreads(); }
    float var = sh[0] * (1.0f / CH);

    float y = d * rsqrtf(var + 1e-5f) * g[t] + b[t];
    if (add) y += add[base];
    out[base] = y;
}

// ---------------- tiled SGEMM:  C[M,N] = A[M,K] @ B[K,N] + bias (+res / gelu) ----
// EPI: 0 = bias only, 1 = bias + residual, 2 = bias + exact GELU
template<int EPI>
__global__ void sgemm_kernel(const float* __restrict__ A,
                             const float* __restrict__ B,
                             const float* __restrict__ bias,
                             const float* __restrict__ res,
                             float* __restrict__ C,
                             int M, int N, int K)
{
    constexpr int BM = 64, BN = 64, BK = 16;
    __shared__ float As[BK][BM];
    __shared__ float Bs[BK][BN];

    int tid = threadIdx.x;             // 256 threads
    int bm  = blockIdx.y * BM;
    int bn  = blockIdx.x * BN;
    int ty  = tid >> 4;                // 0..15
    int tx  = tid & 15;                // 0..15

    float acc[4][4] = {};

    for (int k0 = 0; k0 < K; k0 += BK) {
        #pragma unroll
        for (int i = 0; i < 4; i++) {
            int idx = tid + i * 256;
            int m = idx >> 4, kk = idx & 15;
            int gm = bm + m;
            As[kk][m] = (gm < M) ? A[(size_t)gm * K + (k0 + kk)] : 0.f;
        }
        #pragma unroll
        for (int i = 0; i < 4; i++) {
            int idx = tid + i * 256;
            int kk = idx >> 6, n = idx & 63;
            int gn = bn + n;
            Bs[kk][n] = (gn < N) ? B[(size_t)(k0 + kk) * N + gn] : 0.f;
        }
        __syncthreads();

        #pragma unroll
        for (int kk = 0; kk < BK; kk++) {
            float ra[4], rb[4];
            #pragma unroll
            for (int i = 0; i < 4; i++) ra[i] = As[kk][ty * 4 + i];
            #pragma unroll
            for (int j = 0; j < 4; j++) rb[j] = Bs[kk][tx * 4 + j];
            #pragma unroll
            for (int i = 0; i < 4; i++)
                #pragma unroll
                for (int j = 0; j < 4; j++)
                    acc[i][j] += ra[i] * rb[j];
        }
        __syncthreads();
    }

    #pragma unroll
    for (int i = 0; i < 4; i++) {
        int gm = bm + ty * 4 + i;
        if (gm >= M) continue;
        #pragma unroll
        for (int j = 0; j < 4; j++) {
            int gn = bn + tx * 4 + j;
            if (gn >= N) continue;
            float v = acc[i][j] + bias[gn];
            if (EPI == 1) v += res[(size_t)gm * N + gn];
            if (EPI == 2) v = gelu_f(v);
            C[(size_t)gm * N + gn] = v;
        }
    }
}

// ---------------- deformable sampling: one warp per (b,q,h), lane = channel ----
__global__ void sample_kernel(const float* __restrict__ off,
                              const float* __restrict__ logits,
                              const float* __restrict__ refp,
                              const float* __restrict__ v,
                              float* __restrict__ out)
{
    int gw   = blockIdx.x * 8 + (threadIdx.x >> 5);  // (b*Q+q)*8 + h
    int lane = threadIdx.x & 31;
    int h    = gw & 7;
    int bq   = gw >> 3;                              // b*Q+q

    // softmax over the 12 (level, point) logits of this head
    const float* lg = logits + (size_t)bq * NATT + h * 12;
    float w[12];
    float mx = -1e30f;
    #pragma unroll
    for (int i = 0; i < 12; i++) { w[i] = lg[i]; mx = fmaxf(mx, w[i]); }
    float s = 0.f;
    #pragma unroll
    for (int i = 0; i < 12; i++) { w[i] = __expf(w[i] - mx); s += w[i]; }
    float inv = 1.f / s;

    float rx = refp[(size_t)bq * 2 + 0];
    float ry = refp[(size_t)bq * 2 + 1];

    const float* offp = off + (size_t)bq * NOFF + h * 24;
    int b = bq >> 14;  // Q = 16384 = 2^14
    const float* vb = v + ((size_t)b * NV) * CH + h * DHEAD + lane;

    const int   HsA[3]    = {100, 50, 25};
    const int   startA[3] = {0, 10000, 12500};

    float acc = 0.f;
    #pragma unroll
    for (int l = 0; l < 3; l++) {
        const int Hl = HsA[l], Wl = HsA[l];
        const float fW = (float)Wl, fH = (float)Hl;
        const float* vl = vb + (size_t)startA[l] * CH;
        #pragma unroll
        for (int p = 0; p < 4; p++) {
            float ox = offp[(l * 4 + p) * 2 + 0];
            float oy = offp[(l * 4 + p) * 2 + 1];
            float x = (rx + ox / fW) * fW - 0.5f;
            float y = (ry + oy / fH) * fH - 0.5f;
            float x0f = floorf(x), y0f = floorf(y);
            float lx = x - x0f, ly = y - y0f;
            int x0 = (int)x0f, y0 = (int)y0f;

            bool vx0 = (x0 >= 0)     && (x0 < Wl);
            bool vx1 = (x0 + 1 >= 0) && (x0 + 1 < Wl);
            bool vy0 = (y0 >= 0)     && (y0 < Hl);
            bool vy1 = (y0 + 1 >= 0) && (y0 + 1 < Hl);
            int xc0 = min(max(x0, 0), Wl - 1);
            int xc1 = min(max(x0 + 1, 0), Wl - 1);
            int yc0 = min(max(y0, 0), Hl - 1);
            int yc1 = min(max(y0 + 1, 0), Hl - 1);

            float g00 = 0.f, g01 = 0.f, g10 = 0.f, g11 = 0.f;
            if (vy0) {
                if (vx0) g00 = __ldg(&vl[(size_t)(yc0 * Wl + xc0) * CH]);
                if (vx1) g01 = __ldg(&vl[(size_t)(yc0 * Wl + xc1) * CH]);
            }
            if (vy1) {
                if (vx0) g10 = __ldg(&vl[(size_t)(yc1 * Wl + xc0) * CH]);
                if (vx1) g11 = __ldg(&vl[(size_t)(yc1 * Wl + xc1) * CH]);
            }
            float sampled = g00 * (1.f - lx) * (1.f - ly) + g01 * lx * (1.f - ly)
                          + g10 * (1.f - lx) * ly         + g11 * lx * ly;
            acc += (w[l * 4 + p] * inv) * sampled;
        }
    }
    out[(size_t)bq * CH + h * DHEAD + lane] = acc;
}

// ---------------- launcher ----------------
extern "C" void kernel_launch(void* const* d_in, const int* in_sizes, int n_in,
                              void* d_out, int out_size)
{
    const float* query = (const float*)d_in[0];
    const float* value = (const float*)d_in[1];
    const float* qpos  = (const float*)d_in[2];
    const float* refp  = (const float*)d_in[3];
    // d_in[4] spatial_shapes, d_in[5] level_start_index: constants, unused
    const float* ln1g = (const float*)d_in[6];
    const float* ln1b = (const float*)d_in[7];
    const float* ln2g = (const float*)d_in[8];
    const float* ln2b = (const float*)d_in[9];
    const float* Wv   = (const float*)d_in[10];
    const float* bv   = (const float*)d_in[11];
    const float* Woff = (const float*)d_in[12];
    const float* boff = (const float*)d_in[13];
    const float* Wat  = (const float*)d_in[14];
    const float* bat  = (const float*)d_in[15];
    const float* Wo   = (const float*)d_in[16];
    const float* bo   = (const float*)d_in[17];
    const float* W1   = (const float*)d_in[18];
    const float* b1   = (const float*)d_in[19];
    const float* W2   = (const float*)d_in[20];
    const float* b2   = (const float*)d_in[21];
    float* out = (float*)d_out;

    float *q, *v, *off, *attn, *samp, *x, *h, *hid;
    cudaGetSymbolAddress((void**)&q,    g_q);
    cudaGetSymbolAddress((void**)&v,    g_v);
    cudaGetSymbolAddress((void**)&off,  g_off);
    cudaGetSymbolAddress((void**)&attn, g_attn);
    cudaGetSymbolAddress((void**)&samp, g_samp);
    cudaGetSymbolAddress((void**)&x,    g_x);
    cudaGetSymbolAddress((void**)&h,    g_h);
    cudaGetSymbolAddress((void**)&hid,  g_hid);

    dim3 blk(256);
    auto grid2 = [](int M, int N) { return dim3((N + 63) / 64, (M + 63) / 64); };

    // 1) q = LN1(query) + query_pos
    ln_kernel<<<MQ, 256>>>(query, ln1g, ln1b, qpos, q);
    // 2) v = value @ W_value + b_value
    sgemm_kernel<0><<<grid2(MV, CH), blk>>>(value, Wv, bv, nullptr, v, MV, CH, CH);
    // 3) off = q @ W_off + b_off
    sgemm_kernel<0><<<grid2(MQ, NOFF), blk>>>(q, Woff, boff, nullptr, off, MQ, NOFF, CH);
    // 4) attn logits = q @ W_attn + b_attn
    sgemm_kernel<0><<<grid2(MQ, NATT), blk>>>(q, Wat, bat, nullptr, attn, MQ, NATT, CH);
    // 5) deformable sampling (softmax fused)
    sample_kernel<<<MQ, 256>>>(off, attn, refp, v, samp);
    // 6) x = query + samp @ W_out + b_out
    sgemm_kernel<1><<<grid2(MQ, CH), blk>>>(samp, Wo, bo, query, x, MQ, CH, CH);
    // 7) h = LN2(x)
    ln_kernel<<<MQ, 256>>>(x, ln2g, ln2b, nullptr, h);
    // 8) hid = gelu(h @ W_ffn1 + b_ffn1)
    sgemm_kernel<2><<<grid2(MQ, FFN), blk>>>(h, W1, b1, nullptr, hid, MQ, FFN, CH);
    // 9) out = x + hid @ W_ffn2 + b_ffn2
    sgemm_kernel<1><<<grid2(MQ, CH), blk>>>(hid, W2, b2, x, out, MQ, CH, FFN);
}

// round 3
// speedup vs baseline: 1.9730x; 1.9730x over previous
#include <cuda_runtime.h>
#include <cuda_bf16.h>
#include <math.h>
#include <stdint.h>

// ---------------- problem constants ----------------
#define BATCH 2
#define QLEN  16384
#define CH    256
#define HEADS 8
#define DHEAD 32
#define NV    13125          // 100*100 + 50*50 + 25*25
#define NOFF  192            // H*L*P*2
#define NATT  96             // H*L*P
#define FFN   1024
#define MQ    (BATCH*QLEN)   // 32768
#define MV    (BATCH*NV)     // 26250

// ---------------- scratch (allocation-free) ----------------
__device__ __nv_bfloat16 g_qb   [MQ*CH];    // ln1(query)+pos, bf16 (GEMM A)
__device__ __nv_bfloat16 g_vb   [MV*CH];    // value input converted to bf16
__device__ float         g_v    [MV*CH];    // value projection (sampler input)
__device__ float         g_off  [MQ*NOFF];  // sampling offsets
__device__ float         g_attn [MQ*NATT];  // attention logits
__device__ __nv_bfloat16 g_sampb[MQ*CH];    // deformable attn output, bf16
__device__ float         g_x    [MQ*CH];    // after out-proj residual
__device__ __nv_bfloat16 g_hb   [MQ*CH];    // ln2(x), bf16
__device__ __nv_bfloat16 g_hidb [MQ*FFN];   // ffn hidden, bf16

// transposed bf16 weights  Wt[n][k]
__device__ __nv_bfloat16 g_WvT [CH*CH];
__device__ __nv_bfloat16 g_WoffT[NOFF*CH];
__device__ __nv_bfloat16 g_WatT[NATT*CH];
__device__ __nv_bfloat16 g_WoT [CH*CH];
__device__ __nv_bfloat16 g_W1T [FFN*CH];
__device__ __nv_bfloat16 g_W2T [CH*FFN];

// ---------------- helpers ----------------
__device__ __forceinline__ float gelu_f(float x) {
    return 0.5f * x * (1.0f + erff(x * 0.70710678118654752f));
}

__device__ __forceinline__ void cp_async16(uint32_t dst, const void* src, int sz) {
    asm volatile("cp.async.cg.shared.global [%0], [%1], 16, %2;\n"
                 :: "r"(dst), "l"(src), "r"(sz));
}
__device__ __forceinline__ void cp_commit() { asm volatile("cp.async.commit_group;\n"); }

__device__ __forceinline__ void ldsm_x4(uint32_t& r0, uint32_t& r1, uint32_t& r2, uint32_t& r3,
                                        uint32_t addr) {
    asm volatile("ldmatrix.sync.aligned.m8n8.x4.shared.b16 {%0,%1,%2,%3}, [%4];\n"
                 : "=r"(r0), "=r"(r1), "=r"(r2), "=r"(r3) : "r"(addr));
}
__device__ __forceinline__ void mma_bf16(float* c, uint32_t a0, uint32_t a1, uint32_t a2,
                                         uint32_t a3, uint32_t b0, uint32_t b1) {
    asm volatile("mma.sync.aligned.m16n8k16.row.col.f32.bf16.bf16.f32 "
                 "{%0,%1,%2,%3}, {%4,%5,%6,%7}, {%8,%9}, {%0,%1,%2,%3};\n"
                 : "+f"(c[0]), "+f"(c[1]), "+f"(c[2]), "+f"(c[3])
                 : "r"(a0), "r"(a1), "r"(a2), "r"(a3), "r"(b0), "r"(b1));
}

// ---------------- weight transpose + convert:  Wt[n][k] = bf16(W[k][n]) ------
__global__ void wconv_kernel(const float* __restrict__ W, __nv_bfloat16* __restrict__ Wt,
                             int K, int N) {
    int idx = blockIdx.x * 256 + threadIdx.x;
    if (idx >= N * K) return;
    int n = idx / K, k = idx - n * K;
    Wt[idx] = __float2bfloat16(W[(size_t)k * N + n]);
}

// ---------------- fp32 -> bf16 elementwise ----------------
__global__ void f2b_kernel(const float* __restrict__ in, __nv_bfloat16* __restrict__ out, int n) {
    int idx = blockIdx.x * 256 + threadIdx.x;
    if (idx < n) out[idx] = __float2bfloat16(in[idx]);
}

// ---------------- LayerNorm -> bf16 (one 256-thread block per row, C=256) ----
__global__ void ln_kernel(const float* __restrict__ x,
                          const float* __restrict__ g,
                          const float* __restrict__ b,
                          const float* __restrict__ add,   // optional
                          __nv_bfloat16* __restrict__ out)
{
    int row = blockIdx.x;
    int t   = threadIdx.x;
    size_t base = (size_t)row * CH + t;
    float v = x[base];

    __shared__ float sh[CH];
    sh[t] = v; __syncthreads();
    #pragma unroll
    for (int s = 128; s > 0; s >>= 1) { if (t < s) sh[t] += sh[t + s]; __syncthreads(); }
    float mean = sh[0] * (1.0f / CH);
    __syncthreads();
    float d = v - mean;
    sh[t] = d * d; __syncthreads();
    #pragma unroll
    for (int s = 128; s > 0; s >>= 1) { if (t < s) sh[t] += sh[t + s]; __syncthreads(); }
    float var = sh[0] * (1.0f / CH);

    float y = d * rsqrtf(var + 1e-5f) * g[t] + b[t];
    if (add) y += add[base];
    out[base] = __float2bfloat16(y);
}

// ---------------- bf16 HMMA GEMM: C[M,N] = A[M,K] @ Bt[N,K]^T + bias ---------
// A bf16 row-major [M][K]; Bt bf16 [N][K] (k-contiguous).
// EPI 0: fp32 = acc+bias ; EPI 1: fp32 = acc+bias+res ; EPI 2: bf16 = gelu(acc+bias)
#define LDSM_PAD 40   // padded smem row (bf16 elems): 80B rows -> conflict-free ldmatrix
#define A_ELEMS (128 * LDSM_PAD)
#define B_ELEMS (64  * LDSM_PAD)

template<int EPI>
__global__ void __launch_bounds__(256, 2)
hgemm_kernel(const __nv_bfloat16* __restrict__ A,
             const __nv_bfloat16* __restrict__ Bt,
             const float* __restrict__ bias,
             const float* __restrict__ res,
             float* __restrict__ Cf,
             __nv_bfloat16* __restrict__ Cb,
             int M, int N, int K)
{
    __shared__ __nv_bfloat16 As[2][A_ELEMS];
    __shared__ __nv_bfloat16 Bs[2][B_ELEMS];

    const int tid  = threadIdx.x;
    const int lane = tid & 31;
    const int warp = tid >> 5;
    const int wm   = warp >> 1;   // 0..3  (32 rows each)
    const int wn   = warp & 1;    // 0..1  (32 cols each)
    const int bm   = blockIdx.y * 128;
    const int bn   = blockIdx.x * 64;

    const uint32_t asBase = (uint32_t)__cvta_generic_to_shared(&As[0][0]);
    const uint32_t bsBase = (uint32_t)__cvta_generic_to_shared(&Bs[0][0]);

    // per-thread global-load mapping
    const int aRow0 = tid >> 2;             // + 64 for second
    const int aC8   = (tid & 3) * 8;
    const int bRow  = tid >> 2;
    const int bC8   = (tid & 3) * 8;

    float acc[2][4][4];
    #pragma unroll
    for (int i = 0; i < 2; i++)
        #pragma unroll
        for (int j = 0; j < 4; j++)
            #pragma unroll
            for (int r = 0; r < 4; r++) acc[i][j][r] = 0.f;

    const int KT = K >> 5;   // K / 32

    auto issue = [&](int kt, int buf) {
        #pragma unroll
        for (int i = 0; i < 2; i++) {
            int row = aRow0 + i * 64;
            int gm  = bm + row;
            const __nv_bfloat16* src = A + (size_t)(gm < M ? gm : M - 1) * K + kt * 32 + aC8;
            cp_async16(asBase + (uint32_t)(buf * A_ELEMS + row * LDSM_PAD + aC8) * 2,
                       src, gm < M ? 16 : 0);
        }
        {
            int gn = bn + bRow;
            const __nv_bfloat16* src = Bt + (size_t)(gn < N ? gn : N - 1) * K + kt * 32 + bC8;
            cp_async16(bsBase + (uint32_t)(buf * B_ELEMS + bRow * LDSM_PAD + bC8) * 2,
                       src, gn < N ? 16 : 0);
        }
        cp_commit();
    };

    issue(0, 0);
    int buf = 0;

    for (int kt = 0; kt < KT; kt++) {
        if (kt + 1 < KT) {
            issue(kt + 1, buf ^ 1);
            asm volatile("cp.async.wait_group 1;\n");
        } else {
            asm volatile("cp.async.wait_group 0;\n");
        }
        __syncthreads();

        const uint32_t aB = asBase + (uint32_t)(buf * A_ELEMS) * 2;
        const uint32_t bB = bsBase + (uint32_t)(buf * B_ELEMS) * 2;

        #pragma unroll
        for (int ks = 0; ks < 2; ks++) {
            uint32_t a[2][4];
            #pragma unroll
            for (int mt = 0; mt < 2; mt++) {
                uint32_t addr = aB + (uint32_t)((wm * 32 + mt * 16 + (lane & 15)) * LDSM_PAD
                                                + ks * 16 + (lane >> 4) * 8) * 2;
                ldsm_x4(a[mt][0], a[mt][1], a[mt][2], a[mt][3], addr);
            }
            uint32_t b[4][2];
            #pragma unroll
            for (int np = 0; np < 2; np++) {
                int g = lane >> 3;
                uint32_t addr = bB + (uint32_t)((wn * 32 + np * 16 + (g >> 1) * 8 + (lane & 7)) * LDSM_PAD
                                                + ks * 16 + (g & 1) * 8) * 2;
                uint32_t r0, r1, r2, r3;
                ldsm_x4(r0, r1, r2, r3, addr);
                b[np * 2 + 0][0] = r0; b[np * 2 + 0][1] = r1;
                b[np * 2 + 1][0] = r2; b[np * 2 + 1][1] = r3;
            }
            #pragma unroll
            for (int mt = 0; mt < 2; mt++)
                #pragma unroll
                for (int nt = 0; nt < 4; nt++)
                    mma_bf16(acc[mt][nt], a[mt][0], a[mt][1], a[mt][2], a[mt][3],
                             b[nt][0], b[nt][1]);
        }
        __syncthreads();
        buf ^= 1;
    }

    // epilogue
    #pragma unroll
    for (int mt = 0; mt < 2; mt++) {
        #pragma unroll
        for (int nt = 0; nt < 4; nt++) {
            int m0 = bm + wm * 32 + mt * 16 + (lane >> 2);
            int n0 = bn + wn * 32 + nt * 8 + (lane & 3) * 2;
            #pragma unroll
            for (int half = 0; half < 2; half++) {
                int gm = m0 + half * 8;
                if (gm >= M) continue;
                #pragma unroll
                for (int c = 0; c < 2; c++) {
                    int gn = n0 + c;
                    if (gn >= N) continue;
                    float v = acc[mt][nt][half * 2 + c] + bias[gn];
                    if (EPI == 1) v += res[(size_t)gm * N + gn];
                    if (EPI == 2) {
                        Cb[(size_t)gm * N + gn] = __float2bfloat16(gelu_f(v));
                    } else {
                        Cf[(size_t)gm * N + gn] = v;
                    }
                }
            }
        }
    }
}

// ---------------- deformable sampling: one warp per (b,q,h), lane = channel ----
__global__ void sample_kernel(const float* __restrict__ off,
                              const float* __restrict__ logits,
                              const float* __restrict__ refp,
                              const float* __restrict__ v,
                              __nv_bfloat16* __restrict__ out)
{
    int gw   = blockIdx.x * 8 + (threadIdx.x >> 5);  // (b*Q+q)*8 + h
    int lane = threadIdx.x & 31;
    int h    = gw & 7;
    int bq   = gw >> 3;                              // b*Q+q

    // softmax over the 12 (level, point) logits of this head
    const float* lg = logits + (size_t)bq * NATT + h * 12;
    float w[12];
    float mx = -1e30f;
    #pragma unroll
    for (int i = 0; i < 12; i++) { w[i] = lg[i]; mx = fmaxf(mx, w[i]); }
    float s = 0.f;
    #pragma unroll
    for (int i = 0; i < 12; i++) { w[i] = __expf(w[i] - mx); s += w[i]; }
    float inv = 1.f / s;

    float rx = refp[(size_t)bq * 2 + 0];
    float ry = refp[(size_t)bq * 2 + 1];

    const float* offp = off + (size_t)bq * NOFF + h * 24;
    int b = bq >> 14;  // Q = 16384 = 2^14
    const float* vb = v + ((size_t)b * NV) * CH + h * DHEAD + lane;

    const int HsA[3]    = {100, 50, 25};
    const int startA[3] = {0, 10000, 12500};

    float acc = 0.f;
    #pragma unroll
    for (int l = 0; l < 3; l++) {
        const int Hl = HsA[l], Wl = HsA[l];
        const float fW = (float)Wl, fH = (float)Hl;
        const float* vl = vb + (size_t)startA[l] * CH;
        #pragma unroll
        for (int p = 0; p < 4; p++) {
            float ox = offp[(l * 4 + p) * 2 + 0];
            float oy = offp[(l * 4 + p) * 2 + 1];
            float x = (rx + ox / fW) * fW - 0.5f;
            float y = (ry + oy / fH) * fH - 0.5f;
            float x0f = floorf(x), y0f = floorf(y);
            float lx = x - x0f, ly = y - y0f;
            int x0 = (int)x0f, y0 = (int)y0f;

            bool vx0 = (x0 >= 0)     && (x0 < Wl);
            bool vx1 = (x0 + 1 >= 0) && (x0 + 1 < Wl);
            bool vy0 = (y0 >= 0)     && (y0 < Hl);
            bool vy1 = (y0 + 1 >= 0) && (y0 + 1 < Hl);
            int xc0 = min(max(x0, 0), Wl - 1);
            int xc1 = min(max(x0 + 1, 0), Wl - 1);
            int yc0 = min(max(y0, 0), Hl - 1);
            int yc1 = min(max(y0 + 1, 0), Hl - 1);

            float g00 = 0.f, g01 = 0.f, g10 = 0.f, g11 = 0.f;
            if (vy0) {
                if (vx0) g00 = __ldg(&vl[(size_t)(yc0 * Wl + xc0) * CH]);
                if (vx1) g01 = __ldg(&vl[(size_t)(yc0 * Wl + xc1) * CH]);
            }
            if (vy1) {
                if (vx0) g10 = __ldg(&vl[(size_t)(yc1 * Wl + xc0) * CH]);
                if (vx1) g11 = __ldg(&vl[(size_t)(yc1 * Wl + xc1) * CH]);
            }
            float sampled = g00 * (1.f - lx) * (1.f - ly) + g01 * lx * (1.f - ly)
                          + g10 * (1.f - lx) * ly         + g11 * lx * ly;
            acc += (w[l * 4 + p] * inv) * sampled;
        }
    }
    out[(size_t)bq * CH + h * DHEAD + lane] = __float2bfloat16(acc);
}

// ---------------- launcher ----------------
extern "C" void kernel_launch(void* const* d_in, const int* in_sizes, int n_in,
                              void* d_out, int out_size)
{
    const float* query = (const float*)d_in[0];
    const float* value = (const float*)d_in[1];
    const float* qpos  = (const float*)d_in[2];
    const float* refp  = (const float*)d_in[3];
    const float* ln1g = (const float*)d_in[6];
    const float* ln1b = (const float*)d_in[7];
    const float* ln2g = (const float*)d_in[8];
    const float* ln2b = (const float*)d_in[9];
    const float* Wv   = (const float*)d_in[10];
    const float* bv   = (const float*)d_in[11];
    const float* Woff = (const float*)d_in[12];
    const float* boff = (const float*)d_in[13];
    const float* Wat  = (const float*)d_in[14];
    const float* bat  = (const float*)d_in[15];
    const float* Wo   = (const float*)d_in[16];
    const float* bo   = (const float*)d_in[17];
    const float* W1   = (const float*)d_in[18];
    const float* b1   = (const float*)d_in[19];
    const float* W2   = (const float*)d_in[20];
    const float* b2   = (const float*)d_in[21];
    float* out = (float*)d_out;

    __nv_bfloat16 *qb, *vbf, *sampb, *hb, *hidb;
    __nv_bfloat16 *WvT, *WoffT, *WatT, *WoT, *W1T, *W2T;
    float *v, *off, *attn, *x;
    cudaGetSymbolAddress((void**)&qb,    g_qb);
    cudaGetSymbolAddress((void**)&vbf,   g_vb);
    cudaGetSymbolAddress((void**)&v,     g_v);
    cudaGetSymbolAddress((void**)&off,   g_off);
    cudaGetSymbolAddress((void**)&attn,  g_attn);
    cudaGetSymbolAddress((void**)&sampb, g_sampb);
    cudaGetSymbolAddress((void**)&x,     g_x);
    cudaGetSymbolAddress((void**)&hb,    g_hb);
    cudaGetSymbolAddress((void**)&hidb,  g_hidb);
    cudaGetSymbolAddress((void**)&WvT,   g_WvT);
    cudaGetSymbolAddress((void**)&WoffT, g_WoffT);
    cudaGetSymbolAddress((void**)&WatT,  g_WatT);
    cudaGetSymbolAddress((void**)&WoT,   g_WoT);
    cudaGetSymbolAddress((void**)&W1T,   g_W1T);
    cudaGetSymbolAddress((void**)&W2T,   g_W2T);

    auto wgrid = [](int K, int N) { return dim3((N * K + 255) / 256); };
    auto ggrid = [](int M, int N) { return dim3((N + 63) / 64, (M + 127) / 128); };

    // weight transpose/convert (bf16, [N][K])
    wconv_kernel<<<wgrid(CH, CH),   256>>>(Wv,   WvT,   CH,  CH);
    wconv_kernel<<<wgrid(CH, NOFF), 256>>>(Woff, WoffT, CH,  NOFF);
    wconv_kernel<<<wgrid(CH, NATT), 256>>>(Wat,  WatT,  CH,  NATT);
    wconv_kernel<<<wgrid(CH, CH),   256>>>(Wo,   WoT,   CH,  CH);
    wconv_kernel<<<wgrid(CH, FFN),  256>>>(W1,   W1T,   CH,  FFN);
    wconv_kernel<<<wgrid(FFN, CH),  256>>>(W2,   W2T,   FFN, CH);

    // value -> bf16
    f2b_kernel<<<(MV * CH + 255) / 256, 256>>>(value, vbf, MV * CH);

    // 1) q = LN1(query) + query_pos  (bf16)
    ln_kernel<<<MQ, 256>>>(query, ln1g, ln1b, qpos, qb);
    // 2) v = value @ W_value + b_value  (fp32)
    hgemm_kernel<0><<<ggrid(MV, CH), 256>>>(vbf, WvT, bv, nullptr, v, nullptr, MV, CH, CH);
    // 3) off = q @ W_off + b_off
    hgemm_kernel<0><<<ggrid(MQ, NOFF), 256>>>(qb, WoffT, boff, nullptr, off, nullptr, MQ, NOFF, CH);
    // 4) attn logits = q @ W_attn + b_attn
    hgemm_kernel<0><<<ggrid(MQ, NATT), 256>>>(qb, WatT, bat, nullptr, attn, nullptr, MQ, NATT, CH);
    // 5) deformable sampling (softmax fused) -> bf16
    sample_kernel<<<MQ, 256>>>(off, attn, refp, v, sampb);
    // 6) x = query + samp @ W_out + b_out  (fp32)
    hgemm_kernel<1><<<ggrid(MQ, CH), 256>>>(sampb, WoT, bo, query, x, nullptr, MQ, CH, CH);
    // 7) h = LN2(x)  (bf16)
    ln_kernel<<<MQ, 256>>>(x, ln2g, ln2b, nullptr, hb);
    // 8) hid = gelu(h @ W_ffn1 + b_ffn1)  (bf16)
    hgemm_kernel<2><<<ggrid(MQ, FFN), 256>>>(hb, W1T, b1, nullptr, nullptr, hidb, MQ, FFN, CH);
    // 9) out = x + hid @ W_ffn2 + b_ffn2  (fp32)
    hgemm_kernel<1><<<ggrid(MQ, CH), 256>>>(hidb, W2T, b2, x, out, nullptr, MQ, CH, FFN);
}

// round 4
// speedup vs baseline: 3.2185x; 1.6313x over previous
#include <cuda_runtime.h>
#include <cuda_bf16.h>
#include <math.h>
#include <stdint.h>

// ---------------- problem constants ----------------
#define BATCH 2
#define QLEN  16384
#define CH    256
#define HEADS 8
#define DHEAD 32
#define NV    13125          // 100*100 + 50*50 + 25*25
#define NOA   288            // 192 offsets + 96 attn logits
#define FFN   1024
#define MQ    (BATCH*QLEN)   // 32768
#define MV    (BATCH*NV)     // 26250

// ---------------- scratch (allocation-free) ----------------
__device__ __nv_bfloat16 g_qb  [MQ*CH];    // ln1(query)+pos, bf16
__device__ __nv_bfloat16 g_vb  [MV*CH];    // value input bf16 (GEMM A)
__device__ __nv_bfloat16 g_vp  [MV*CH];    // value projection, bf16 (sampler input)
__device__ float         g_oa  [MQ*NOA];   // [offsets(192) | attn logits(96)]
__device__ __nv_bfloat16 g_sampb[MQ*CH];   // deformable attn output, bf16
__device__ float         g_x   [MQ*CH];    // after out-proj residual
__device__ __nv_bfloat16 g_hb  [MQ*CH];    // ln2(x), bf16
__device__ __nv_bfloat16 g_hidb[MQ*FFN];   // ffn hidden, bf16

// transposed bf16 weights Wt[n][k]
__device__ __nv_bfloat16 g_WvT [CH*CH];
__device__ __nv_bfloat16 g_WoaT[NOA*CH];
__device__ __nv_bfloat16 g_WoT [CH*CH];
__device__ __nv_bfloat16 g_W1T [FFN*CH];
__device__ __nv_bfloat16 g_W2T [CH*FFN];
__device__ float         g_boa [NOA];

// ---------------- helpers ----------------
__device__ __forceinline__ float gelu_f(float x) {
    return 0.5f * x * (1.0f + erff(x * 0.70710678118654752f));
}
__device__ __forceinline__ void cp_async16(uint32_t dst, const void* src, int sz) {
    asm volatile("cp.async.cg.shared.global [%0], [%1], 16, %2;\n"
                 :: "r"(dst), "l"(src), "r"(sz));
}
__device__ __forceinline__ void cp_commit() { asm volatile("cp.async.commit_group;\n"); }
__device__ __forceinline__ void ldsm_x4(uint32_t& r0, uint32_t& r1, uint32_t& r2, uint32_t& r3,
                                        uint32_t addr) {
    asm volatile("ldmatrix.sync.aligned.m8n8.x4.shared.b16 {%0,%1,%2,%3}, [%4];\n"
                 : "=r"(r0), "=r"(r1), "=r"(r2), "=r"(r3) : "r"(addr));
}
__device__ __forceinline__ void mma_bf16(float* c, uint32_t a0, uint32_t a1, uint32_t a2,
                                         uint32_t a3, uint32_t b0, uint32_t b1) {
    asm volatile("mma.sync.aligned.m16n8k16.row.col.f32.bf16.bf16.f32 "
                 "{%0,%1,%2,%3}, {%4,%5,%6,%7}, {%8,%9}, {%0,%1,%2,%3};\n"
                 : "+f"(c[0]), "+f"(c[1]), "+f"(c[2]), "+f"(c[3])
                 : "r"(a0), "r"(a1), "r"(a2), "r"(a3), "r"(b0), "r"(b1));
}

// ---------------- all weight transposes + concat in ONE kernel ----------------
__global__ void wconv_all(const float* __restrict__ Wv, const float* __restrict__ Woff,
                          const float* __restrict__ Wat, const float* __restrict__ Wo,
                          const float* __restrict__ W1, const float* __restrict__ W2,
                          const float* __restrict__ boff, const float* __restrict__ bat)
{
    int idx = blockIdx.x * 256 + threadIdx.x;
    if (idx < 65536) {
        int n = idx >> 8, k = idx & 255;
        g_WvT[idx] = __float2bfloat16(Wv[k * CH + n]);
        return;
    }
    idx -= 65536;
    if (idx < 73728) {  // 288*256
        int n = idx >> 8, k = idx & 255;
        float w = (n < 192) ? Woff[k * 192 + n] : Wat[k * 96 + (n - 192)];
        g_WoaT[idx] = __float2bfloat16(w);
        return;
    }
    idx -= 73728;
    if (idx < 65536) {
        int n = idx >> 8, k = idx & 255;
        g_WoT[idx] = __float2bfloat16(Wo[k * CH + n]);
        return;
    }
    idx -= 65536;
    if (idx < 262144) {  // W1T [1024][256]
        int n = idx >> 8, k = idx & 255;
        g_W1T[idx] = __float2bfloat16(W1[k * FFN + n]);
        return;
    }
    idx -= 262144;
    if (idx < 262144) {  // W2T [256][1024]
        int n = idx >> 10, k = idx & 1023;
        g_W2T[idx] = __float2bfloat16(W2[k * CH + n]);
        return;
    }
    idx -= 262144;
    if (idx < NOA) g_boa[idx] = (idx < 192) ? boff[idx] : bat[idx - 192];
}
#define WCONV_TOTAL (65536 + 73728 + 65536 + 262144 + 262144 + NOA)

// ---------------- fp32 -> bf16 elementwise ----------------
__global__ void f2b_kernel(const float* __restrict__ in, __nv_bfloat16* __restrict__ out, int n) {
    int idx = blockIdx.x * 256 + threadIdx.x;
    if (idx < n) out[idx] = __float2bfloat16(in[idx]);
}

// ---------------- LayerNorm -> bf16 ----------------
__global__ void ln_kernel(const float* __restrict__ x,
                          const float* __restrict__ g,
                          const float* __restrict__ b,
                          const float* __restrict__ add,
                          __nv_bfloat16* __restrict__ out)
{
    int row = blockIdx.x;
    int t   = threadIdx.x;
    size_t base = (size_t)row * CH + t;
    float v = x[base];

    __shared__ float sh[CH];
    sh[t] = v; __syncthreads();
    #pragma unroll
    for (int s = 128; s > 0; s >>= 1) { if (t < s) sh[t] += sh[t + s]; __syncthreads(); }
    float mean = sh[0] * (1.0f / CH);
    __syncthreads();
    float d = v - mean;
    sh[t] = d * d; __syncthreads();
    #pragma unroll
    for (int s = 128; s > 0; s >>= 1) { if (t < s) sh[t] += sh[t + s]; __syncthreads(); }
    float var = sh[0] * (1.0f / CH);

    float y = d * rsqrtf(var + 1e-5f) * g[t] + b[t];
    if (add) y += add[base];
    out[base] = __float2bfloat16(y);
}

// ---------------- bf16 HMMA GEMM 128x128x32, warp tile 64x32 ------------------
// EPI 0: fp32=acc+bias ; 1: fp32=acc+bias+res ; 2: bf16=gelu(acc+bias) ; 3: bf16=acc+bias
#define LDSM_PAD 40
#define A_ELEMS (128 * LDSM_PAD)
#define B_ELEMS (128 * LDSM_PAD)

template<int EPI>
__global__ void __launch_bounds__(256, 2)
hgemm_kernel(const __nv_bfloat16* __restrict__ A,
             const __nv_bfloat16* __restrict__ Bt,
             const float* __restrict__ bias,
             const float* __restrict__ res,
             float* __restrict__ Cf,
             __nv_bfloat16* __restrict__ Cb,
             int M, int N, int K)
{
    __shared__ __nv_bfloat16 As[2][A_ELEMS];
    __shared__ __nv_bfloat16 Bs[2][B_ELEMS];

    const int tid  = threadIdx.x;
    const int lane = tid & 31;
    const int warp = tid >> 5;
    const int wm   = warp >> 2;   // 0..1 : 64 rows
    const int wn   = warp & 3;    // 0..3 : 32 cols
    const int bm   = blockIdx.y * 128;
    const int bn   = blockIdx.x * 128;

    const uint32_t asBase = (uint32_t)__cvta_generic_to_shared(&As[0][0]);
    const uint32_t bsBase = (uint32_t)__cvta_generic_to_shared(&Bs[0][0]);

    const int row0 = tid >> 2;            // 0..63, +64 second
    const int c8   = (tid & 3) * 8;

    float acc[4][4][4];
    #pragma unroll
    for (int i = 0; i < 4; i++)
        #pragma unroll
        for (int j = 0; j < 4; j++)
            #pragma unroll
            for (int r = 0; r < 4; r++) acc[i][j][r] = 0.f;

    const int KT = K >> 5;

    auto issue = [&](int kt, int buf) {
        #pragma unroll
        for (int i = 0; i < 2; i++) {
            int row = row0 + i * 64;
            int gm  = bm + row;
            const __nv_bfloat16* src = A + (size_t)(gm < M ? gm : M - 1) * K + kt * 32 + c8;
            cp_async16(asBase + (uint32_t)(buf * A_ELEMS + row * LDSM_PAD + c8) * 2,
                       src, gm < M ? 16 : 0);
        }
        #pragma unroll
        for (int i = 0; i < 2; i++) {
            int row = row0 + i * 64;
            int gn  = bn + row;
            const __nv_bfloat16* src = Bt + (size_t)(gn < N ? gn : N - 1) * K + kt * 32 + c8;
            cp_async16(bsBase + (uint32_t)(buf * B_ELEMS + row * LDSM_PAD + c8) * 2,
                       src, gn < N ? 16 : 0);
        }
        cp_commit();
    };

    issue(0, 0);
    int buf = 0;

    for (int kt = 0; kt < KT; kt++) {
        if (kt + 1 < KT) {
            issue(kt + 1, buf ^ 1);
            asm volatile("cp.async.wait_group 1;\n");
        } else {
            asm volatile("cp.async.wait_group 0;\n");
        }
        __syncthreads();

        const uint32_t aB = asBase + (uint32_t)(buf * A_ELEMS) * 2;
        const uint32_t bB = bsBase + (uint32_t)(buf * B_ELEMS) * 2;

        #pragma unroll
        for (int ks = 0; ks < 2; ks++) {
            uint32_t a[4][4];
            #pragma unroll
            for (int mt = 0; mt < 4; mt++) {
                uint32_t addr = aB + (uint32_t)((wm * 64 + mt * 16 + (lane & 15)) * LDSM_PAD
                                                + ks * 16 + (lane >> 4) * 8) * 2;
                ldsm_x4(a[mt][0], a[mt][1], a[mt][2], a[mt][3], addr);
            }
            uint32_t b[4][2];
            #pragma unroll
            for (int np = 0; np < 2; np++) {
                int g = lane >> 3;
                uint32_t addr = bB + (uint32_t)((wn * 32 + np * 16 + (g >> 1) * 8 + (lane & 7)) * LDSM_PAD
                                                + ks * 16 + (g & 1) * 8) * 2;
                uint32_t r0, r1, r2, r3;
                ldsm_x4(r0, r1, r2, r3, addr);
                b[np * 2 + 0][0] = r0; b[np * 2 + 0][1] = r1;
                b[np * 2 + 1][0] = r2; b[np * 2 + 1][1] = r3;
            }
            #pragma unroll
            for (int mt = 0; mt < 4; mt++)
                #pragma unroll
                for (int nt = 0; nt < 4; nt++)
                    mma_bf16(acc[mt][nt], a[mt][0], a[mt][1], a[mt][2], a[mt][3],
                             b[nt][0], b[nt][1]);
        }
        __syncthreads();
        buf ^= 1;
    }

    #pragma unroll
    for (int mt = 0; mt < 4; mt++) {
        #pragma unroll
        for (int nt = 0; nt < 4; nt++) {
            int m0 = bm + wm * 64 + mt * 16 + (lane >> 2);
            int n0 = bn + wn * 32 + nt * 8 + (lane & 3) * 2;
            #pragma unroll
            for (int half = 0; half < 2; half++) {
                int gm = m0 + half * 8;
                if (gm >= M) continue;
                #pragma unroll
                for (int c = 0; c < 2; c++) {
                    int gn = n0 + c;
                    if (gn >= N) continue;
                    float v = acc[mt][nt][half * 2 + c] + bias[gn];
                    if (EPI == 1) v += res[(size_t)gm * N + gn];
                    if (EPI == 2) Cb[(size_t)gm * N + gn] = __float2bfloat16(gelu_f(v));
                    else if (EPI == 3) Cb[(size_t)gm * N + gn] = __float2bfloat16(v);
                    else Cf[(size_t)gm * N + gn] = v;
                }
            }
        }
    }
}

// ---------------- deformable sampling: one warp per (b,q,h), lane = channel ----
__global__ void sample_kernel(const float* __restrict__ oa,
                              const float* __restrict__ refp,
                              const __nv_bfloat16* __restrict__ v,
                              __nv_bfloat16* __restrict__ out)
{
    int gw   = blockIdx.x * 8 + (threadIdx.x >> 5);
    int lane = threadIdx.x & 31;
    int h    = gw & 7;
    int bq   = gw >> 3;

    const float* lg = oa + (size_t)bq * NOA + 192 + h * 12;
    float w[12];
    float mx = -1e30f;
    #pragma unroll
    for (int i = 0; i < 12; i++) { w[i] = lg[i]; mx = fmaxf(mx, w[i]); }
    float s = 0.f;
    #pragma unroll
    for (int i = 0; i < 12; i++) { w[i] = __expf(w[i] - mx); s += w[i]; }
    float inv = 1.f / s;

    float rx = refp[(size_t)bq * 2 + 0];
    float ry = refp[(size_t)bq * 2 + 1];

    const float* offp = oa + (size_t)bq * NOA + h * 24;
    int b = bq >> 14;
    const __nv_bfloat16* vb = v + ((size_t)b * NV) * CH + h * DHEAD + lane;

    const int HsA[3]    = {100, 50, 25};
    const int startA[3] = {0, 10000, 12500};

    float acc = 0.f;
    #pragma unroll
    for (int l = 0; l < 3; l++) {
        const int Hl = HsA[l], Wl = HsA[l];
        const float fW = (float)Wl, fH = (float)Hl;
        const __nv_bfloat16* vl = vb + (size_t)startA[l] * CH;
        #pragma unroll
        for (int p = 0; p < 4; p++) {
            float ox = offp[(l * 4 + p) * 2 + 0];
            float oy = offp[(l * 4 + p) * 2 + 1];
            float x = (rx + ox / fW) * fW - 0.5f;
            float y = (ry + oy / fH) * fH - 0.5f;
            float x0f = floorf(x), y0f = floorf(y);
            float lx = x - x0f, ly = y - y0f;
            int x0 = (int)x0f, y0 = (int)y0f;

            bool vx0 = (x0 >= 0)     && (x0 < Wl);
            bool vx1 = (x0 + 1 >= 0) && (x0 + 1 < Wl);
            bool vy0 = (y0 >= 0)     && (y0 < Hl);
            bool vy1 = (y0 + 1 >= 0) && (y0 + 1 < Hl);
            int xc0 = min(max(x0, 0), Wl - 1);
            int xc1 = min(max(x0 + 1, 0), Wl - 1);
            int yc0 = min(max(y0, 0), Hl - 1);
            int yc1 = min(max(y0 + 1, 0), Hl - 1);

            float g00 = 0.f, g01 = 0.f, g10 = 0.f, g11 = 0.f;
            if (vy0) {
                if (vx0) g00 = __bfloat162float(__ldg(&vl[(size_t)(yc0 * Wl + xc0) * CH]));
                if (vx1) g01 = __bfloat162float(__ldg(&vl[(size_t)(yc0 * Wl + xc1) * CH]));
            }
            if (vy1) {
                if (vx0) g10 = __bfloat162float(__ldg(&vl[(size_t)(yc1 * Wl + xc0) * CH]));
                if (vx1) g11 = __bfloat162float(__ldg(&vl[(size_t)(yc1 * Wl + xc1) * CH]));
            }
            float sampled = g00 * (1.f - lx) * (1.f - ly) + g01 * lx * (1.f - ly)
                          + g10 * (1.f - lx) * ly         + g11 * lx * ly;
            acc += (w[l * 4 + p] * inv) * sampled;
        }
    }
    out[(size_t)bq * CH + h * DHEAD + lane] = __float2bfloat16(acc);
}

// ---------------- launcher ----------------
extern "C" void kernel_launch(void* const* d_in, const int* in_sizes, int n_in,
                              void* d_out, int out_size)
{
    const float* query = (const float*)d_in[0];
    const float* value = (const float*)d_in[1];
    const float* qpos  = (const float*)d_in[2];
    const float* refp  = (const float*)d_in[3];
    const float* ln1g = (const float*)d_in[6];
    const float* ln1b = (const float*)d_in[7];
    const float* ln2g = (const float*)d_in[8];
    const float* ln2b = (const float*)d_in[9];
    const float* Wv   = (const float*)d_in[10];
    const float* bv   = (const float*)d_in[11];
    const float* Woff = (const float*)d_in[12];
    const float* boff = (const float*)d_in[13];
    const float* Wat  = (const float*)d_in[14];
    const float* bat  = (const float*)d_in[15];
    const float* Wo   = (const float*)d_in[16];
    const float* bo   = (const float*)d_in[17];
    const float* W1   = (const float*)d_in[18];
    const float* b1   = (const float*)d_in[19];
    const float* W2   = (const float*)d_in[20];
    const float* b2   = (const float*)d_in[21];
    float* out = (float*)d_out;

    __nv_bfloat16 *qb, *vbf, *vp, *sampb, *hb, *hidb;
    __nv_bfloat16 *WvT, *WoaT, *WoT, *W1T, *W2T;
    float *oa, *x, *boa;
    cudaGetSymbolAddress((void**)&qb,    g_qb);
    cudaGetSymbolAddress((void**)&vbf,   g_vb);
    cudaGetSymbolAddress((void**)&vp,    g_vp);
    cudaGetSymbolAddress((void**)&oa,    g_oa);
    cudaGetSymbolAddress((void**)&sampb, g_sampb);
    cudaGetSymbolAddress((void**)&x,     g_x);
    cudaGetSymbolAddress((void**)&hb,    g_hb);
    cudaGetSymbolAddress((void**)&hidb,  g_hidb);
    cudaGetSymbolAddress((void**)&WvT,   g_WvT);
    cudaGetSymbolAddress((void**)&WoaT,  g_WoaT);
    cudaGetSymbolAddress((void**)&WoT,   g_WoT);
    cudaGetSymbolAddress((void**)&W1T,   g_W1T);
    cudaGetSymbolAddress((void**)&W2T,   g_W2T);
    cudaGetSymbolAddress((void**)&boa,   g_boa);

    auto ggrid = [](int M, int N) { return dim3((N + 127) / 128, (M + 127) / 128); };

    wconv_all<<<(WCONV_TOTAL + 255) / 256, 256>>>(Wv, Woff, Wat, Wo, W1, W2, boff, bat);
    f2b_kernel<<<(MV * CH + 255) / 256, 256>>>(value, vbf, MV * CH);
    ln_kernel<<<MQ, 256>>>(query, ln1g, ln1b, qpos, qb);
    hgemm_kernel<3><<<ggrid(MV, CH), 256>>>(vbf, WvT, bv, nullptr, nullptr, vp, MV, CH, CH);
    hgemm_kernel<0><<<ggrid(MQ, NOA), 256>>>(qb, WoaT, boa, nullptr, oa, nullptr, MQ, NOA, CH);
    sample_kernel<<<MQ, 256>>>(oa, refp, vp, sampb);                       // 6th: profiled
    hgemm_kernel<1><<<ggrid(MQ, CH), 256>>>(sampb, WoT, bo, query, x, nullptr, MQ, CH, CH);
    ln_kernel<<<MQ, 256>>>(x, ln2g, ln2b, nullptr, hb);
    hgemm_kernel<2><<<ggrid(MQ, FFN), 256>>>(hb, W1T, b1, nullptr, nullptr, hidb, MQ, FFN, CH);
    hgemm_kernel<1><<<ggrid(MQ, CH), 256>>>(hidb, W2T, b2, x, out, nullptr, MQ, CH, FFN);
}

// round 6
// speedup vs baseline: 3.2533x; 1.0108x over previous
#include <cuda_runtime.h>
#include <cuda_bf16.h>
#include <math.h>
#include <stdint.h>

// ---------------- problem constants ----------------
#define BATCH 2
#define QLEN  16384
#define CH    256
#define HEADS 8
#define DHEAD 32
#define NV    13125          // 100*100 + 50*50 + 25*25
#define NOA   288            // 192 offsets + 96 attn logits
#define FFN   1024
#define MQ    (BATCH*QLEN)   // 32768
#define MV    (BATCH*NV)     // 26250

// ---------------- scratch (allocation-free) ----------------
__device__ __nv_bfloat16 g_qb  [MQ*CH];
__device__ __nv_bfloat16 g_vb  [MV*CH];
__device__ __nv_bfloat16 g_vp  [MV*CH];
__device__ float         g_oa  [MQ*NOA];
__device__ __nv_bfloat16 g_sampb[MQ*CH];
__device__ float         g_x   [MQ*CH];
__device__ __nv_bfloat16 g_hb  [MQ*CH];
__device__ __nv_bfloat16 g_hidb[MQ*FFN];

__device__ __nv_bfloat16 g_WvT [CH*CH];
__device__ __nv_bfloat16 g_WoaT[NOA*CH];
__device__ __nv_bfloat16 g_WoT [CH*CH];
__device__ __nv_bfloat16 g_W1T [FFN*CH];
__device__ __nv_bfloat16 g_W2T [CH*FFN];
__device__ float         g_boa [NOA];

// ---------------- helpers ----------------
__device__ __forceinline__ float gelu_f(float x) {
    return 0.5f * x * (1.0f + erff(x * 0.70710678118654752f));
}
__device__ __forceinline__ void cp_async16(uint32_t dst, const void* src, int sz) {
    asm volatile("cp.async.cg.shared.global [%0], [%1], 16, %2;\n"
                 :: "r"(dst), "l"(src), "r"(sz));
}
__device__ __forceinline__ void cp_commit() { asm volatile("cp.async.commit_group;\n"); }
__device__ __forceinline__ void ldsm_x4(uint32_t& r0, uint32_t& r1, uint32_t& r2, uint32_t& r3,
                                        uint32_t addr) {
    asm volatile("ldmatrix.sync.aligned.m8n8.x4.shared.b16 {%0,%1,%2,%3}, [%4];\n"
                 : "=r"(r0), "=r"(r1), "=r"(r2), "=r"(r3) : "r"(addr));
}
__device__ __forceinline__ void mma_bf16(float* c, uint32_t a0, uint32_t a1, uint32_t a2,
                                         uint32_t a3, uint32_t b0, uint32_t b1) {
    asm volatile("mma.sync.aligned.m16n8k16.row.col.f32.bf16.bf16.f32 "
                 "{%0,%1,%2,%3}, {%4,%5,%6,%7}, {%8,%9}, {%0,%1,%2,%3};\n"
                 : "+f"(c[0]), "+f"(c[1]), "+f"(c[2]), "+f"(c[3])
                 : "r"(a0), "r"(a1), "r"(a2), "r"(a3), "r"(b0), "r"(b1));
}

// ---------------- all weight transposes + concat in ONE kernel ----------------
__global__ void wconv_all(const float* __restrict__ Wv, const float* __restrict__ Woff,
                          const float* __restrict__ Wat, const float* __restrict__ Wo,
                          const float* __restrict__ W1, const float* __restrict__ W2,
                          const float* __restrict__ boff, const float* __restrict__ bat)
{
    int idx = blockIdx.x * 256 + threadIdx.x;
    if (idx < 65536) {
        int n = idx >> 8, k = idx & 255;
        g_WvT[idx] = __float2bfloat16(Wv[k * CH + n]);
        return;
    }
    idx -= 65536;
    if (idx < 73728) {
        int n = idx >> 8, k = idx & 255;
        float w = (n < 192) ? Woff[k * 192 + n] : Wat[k * 96 + (n - 192)];
        g_WoaT[idx] = __float2bfloat16(w);
        return;
    }
    idx -= 73728;
    if (idx < 65536) {
        int n = idx >> 8, k = idx & 255;
        g_WoT[idx] = __float2bfloat16(Wo[k * CH + n]);
        return;
    }
    idx -= 65536;
    if (idx < 262144) {
        int n = idx >> 8, k = idx & 255;
        g_W1T[idx] = __float2bfloat16(W1[k * FFN + n]);
        return;
    }
    idx -= 262144;
    if (idx < 262144) {
        int n = idx >> 10, k = idx & 1023;
        g_W2T[idx] = __float2bfloat16(W2[k * CH + n]);
        return;
    }
    idx -= 262144;
    if (idx < NOA) g_boa[idx] = (idx < 192) ? boff[idx] : bat[idx - 192];
}
#define WCONV_TOTAL (65536 + 73728 + 65536 + 262144 + 262144 + NOA)

// ---------------- fp32 -> bf16 elementwise ----------------
__global__ void f2b_kernel(const float* __restrict__ in, __nv_bfloat16* __restrict__ out, int n) {
    int idx = blockIdx.x * 256 + threadIdx.x;
    if (idx < n) out[idx] = __float2bfloat16(in[idx]);
}

// ---------------- LayerNorm -> bf16 ----------------
__global__ void ln_kernel(const float* __restrict__ x,
                          const float* __restrict__ g,
                          const float* __restrict__ b,
                          const float* __restrict__ add,
                          __nv_bfloat16* __restrict__ out)
{
    int row = blockIdx.x;
    int t   = threadIdx.x;
    size_t base = (size_t)row * CH + t;
    float v = x[base];

    __shared__ float sh[CH];
    sh[t] = v; __syncthreads();
    #pragma unroll
    for (int s = 128; s > 0; s >>= 1) { if (t < s) sh[t] += sh[t + s]; __syncthreads(); }
    float mean = sh[0] * (1.0f / CH);
    __syncthreads();
    float d = v - mean;
    sh[t] = d * d; __syncthreads();
    #pragma unroll
    for (int s = 128; s > 0; s >>= 1) { if (t < s) sh[t] += sh[t + s]; __syncthreads(); }
    float var = sh[0] * (1.0f / CH);

    float y = d * rsqrtf(var + 1e-5f) * g[t] + b[t];
    if (add) y += add[base];
    out[base] = __float2bfloat16(y);
}

// ---------------- bf16 HMMA GEMM 128x128x32, 3-stage cp.async pipeline --------
// EPI 0: fp32=acc+bias ; 1: fp32=acc+bias+res ; 2: bf16=gelu(acc+bias) ; 3: bf16=acc+bias
#define LDSM_PAD 40
#define A_ELEMS (128 * LDSM_PAD)
#define B_ELEMS (128 * LDSM_PAD)
#define STAGES  3

template<int EPI>
__global__ void __launch_bounds__(256, 2)
hgemm_kernel(const __nv_bfloat16* __restrict__ A,
             const __nv_bfloat16* __restrict__ Bt,
             const float* __restrict__ bias,
             const float* __restrict__ res,
             float* __restrict__ Cf,
             __nv_bfloat16* __restrict__ Cb,
             int M, int N, int K)
{
    __shared__ __nv_bfloat16 As[STAGES][A_ELEMS];
    __shared__ __nv_bfloat16 Bs[STAGES][B_ELEMS];

    const int tid  = threadIdx.x;
    const int lane = tid & 31;
    const int warp = tid >> 5;
    const int wm   = warp >> 2;   // 0..1 : 64 rows
    const int wn   = warp & 3;    // 0..3 : 32 cols
    const int bm   = blockIdx.y * 128;
    const int bn   = blockIdx.x * 128;

    const uint32_t asBase = (uint32_t)__cvta_generic_to_shared(&As[0][0]);
    const uint32_t bsBase = (uint32_t)__cvta_generic_to_shared(&Bs[0][0]);

    const int row0 = tid >> 2;
    const int c8   = (tid & 3) * 8;

    float acc[4][4][4];
    #pragma unroll
    for (int i = 0; i < 4; i++)
        #pragma unroll
        for (int j = 0; j < 4; j++)
            #pragma unroll
            for (int r = 0; r < 4; r++) acc[i][j][r] = 0.f;

    const int KT = K >> 5;

    auto issue = [&](int kt, int buf) {
        #pragma unroll
        for (int i = 0; i < 2; i++) {
            int row = row0 + i * 64;
            int gm  = bm + row;
            const __nv_bfloat16* src = A + (size_t)(gm < M ? gm : M - 1) * K + kt * 32 + c8;
            cp_async16(asBase + (uint32_t)(buf * A_ELEMS + row * LDSM_PAD + c8) * 2,
                       src, gm < M ? 16 : 0);
        }
        #pragma unroll
        for (int i = 0; i < 2; i++) {
            int row = row0 + i * 64;
            int gn  = bn + row;
            const __nv_bfloat16* src = Bt + (size_t)(gn < N ? gn : N - 1) * K + kt * 32 + c8;
            cp_async16(bsBase + (uint32_t)(buf * B_ELEMS + row * LDSM_PAD + c8) * 2,
                       src, gn < N ? 16 : 0);
        }
        cp_commit();
    };

    issue(0, 0);
    if (KT > 1) issue(1, 1);

    int buf = 0;           // buffer of current kt
    int nxt = (KT > 2) ? 2 : 0;  // buffer to fill with kt+2

    for (int kt = 0; kt < KT; kt++) {
        if (kt + 1 < KT) asm volatile("cp.async.wait_group 1;\n");
        else             asm volatile("cp.async.wait_group 0;\n");
        __syncthreads();                       // tile kt visible; compute kt-1 retired

        if (kt + 2 < KT) issue(kt + 2, nxt);   // refills slot used by kt-1

        const uint32_t aB = asBase + (uint32_t)(buf * A_ELEMS) * 2;
        const uint32_t bB = bsBase + (uint32_t)(buf * B_ELEMS) * 2;

        #pragma unroll
        for (int ks = 0; ks < 2; ks++) {
            uint32_t a[4][4];
            #pragma unroll
            for (int mt = 0; mt < 4; mt++) {
                uint32_t addr = aB + (uint32_t)((wm * 64 + mt * 16 + (lane & 15)) * LDSM_PAD
                                                + ks * 16 + (lane >> 4) * 8) * 2;
                ldsm_x4(a[mt][0], a[mt][1], a[mt][2], a[mt][3], addr);
            }
            uint32_t b[4][2];
            #pragma unroll
            for (int np = 0; np < 2; np++) {
                int g = lane >> 3;
                uint32_t addr = bB + (uint32_t)((wn * 32 + np * 16 + (g >> 1) * 8 + (lane & 7)) * LDSM_PAD
                                                + ks * 16 + (g & 1) * 8) * 2;
                uint32_t r0, r1, r2, r3;
                ldsm_x4(r0, r1, r2, r3, addr);
                b[np * 2 + 0][0] = r0; b[np * 2 + 0][1] = r1;
                b[np * 2 + 1][0] = r2; b[np * 2 + 1][1] = r3;
            }
            #pragma unroll
            for (int mt = 0; mt < 4; mt++)
                #pragma unroll
                for (int nt = 0; nt < 4; nt++)
                    mma_bf16(acc[mt][nt], a[mt][0], a[mt][1], a[mt][2], a[mt][3],
                             b[nt][0], b[nt][1]);
        }

        buf = (buf + 1 == STAGES) ? 0 : buf + 1;
        nxt = (nxt + 1 == STAGES) ? 0 : nxt + 1;
    }

    #pragma unroll
    for (int mt = 0; mt < 4; mt++) {
        #pragma unroll
        for (int nt = 0; nt < 4; nt++) {
            int m0 = bm + wm * 64 + mt * 16 + (lane >> 2);
            int n0 = bn + wn * 32 + nt * 8 + (lane & 3) * 2;
            #pragma unroll
            for (int half = 0; half < 2; half++) {
                int gm = m0 + half * 8;
                if (gm >= M) continue;
                #pragma unroll
                for (int c = 0; c < 2; c++) {
                    int gn = n0 + c;
                    if (gn >= N) continue;
                    float v = acc[mt][nt][half * 2 + c] + bias[gn];
                    if (EPI == 1) v += res[(size_t)gm * N + gn];
                    if (EPI == 2) Cb[(size_t)gm * N + gn] = __float2bfloat16(gelu_f(v));
                    else if (EPI == 3) Cb[(size_t)gm * N + gn] = __float2bfloat16(v);
                    else Cf[(size_t)gm * N + gn] = v;
                }
            }
        }
    }
}

// ---------------- deformable sampling: branch-free, high MLP -------------------
__global__ void sample_kernel(const float* __restrict__ oa,
                              const float* __restrict__ refp,
                              const __nv_bfloat16* __restrict__ v,
                              __nv_bfloat16* __restrict__ out)
{
    int gw   = blockIdx.x * 8 + (threadIdx.x >> 5);
    int lane = threadIdx.x & 31;
    int h    = gw & 7;
    int bq   = gw >> 3;

    // softmax over the 12 (level,point) logits of this head
    const float* lg = oa + (size_t)bq * NOA + 192 + h * 12;
    float w[12];
    float mx = -1e30f;
    #pragma unroll
    for (int i = 0; i < 12; i++) { w[i] = lg[i]; mx = fmaxf(mx, w[i]); }
    float s = 0.f;
    #pragma unroll
    for (int i = 0; i < 12; i++) { w[i] = __expf(w[i] - mx); s += w[i]; }
    float inv = 1.f / s;

    float rx = refp[(size_t)bq * 2 + 0];
    float ry = refp[(size_t)bq * 2 + 1];

    const float* offp = oa + (size_t)bq * NOA + h * 24;
    int b = bq >> 14;
    const __nv_bfloat16* vb = v + ((size_t)b * NV) * CH + h * DHEAD + lane;

    const int HsA[3]    = {100, 50, 25};
    const int startA[3] = {0, 10000, 12500};

    float acc = 0.f;
    #pragma unroll
    for (int l = 0; l < 3; l++) {
        const int Wl = HsA[l];
        const float fW = (float)Wl;
        const __nv_bfloat16* vl = vb + (size_t)startA[l] * CH;
        #pragma unroll
        for (int p = 0; p < 4; p++) {
            float ox = offp[(l * 4 + p) * 2 + 0];
            float oy = offp[(l * 4 + p) * 2 + 1];
            float x = (rx + ox / fW) * fW - 0.5f;
            float y = (ry + oy / fW) * fW - 0.5f;
            float x0f = floorf(x), y0f = floorf(y);
            float lx = x - x0f, ly = y - y0f;
            int x0 = (int)x0f, y0 = (int)y0f;

            // validity as 0/1 multipliers (branch-free)
            float mx0 = (x0 >= 0     && x0 < Wl)     ? 1.f : 0.f;
            float mx1 = (x0 + 1 >= 0 && x0 + 1 < Wl) ? 1.f : 0.f;
            float my0 = (y0 >= 0     && y0 < Wl)     ? 1.f : 0.f;
            float my1 = (y0 + 1 >= 0 && y0 + 1 < Wl) ? 1.f : 0.f;

            int xc0 = min(max(x0, 0), Wl - 1);
            int xc1 = min(max(x0 + 1, 0), Wl - 1);
            int yc0 = min(max(y0, 0), Wl - 1);
            int yc1 = min(max(y0 + 1, 0), Wl - 1);

            // unconditional clamped gathers -> ptxas can batch (high MLP)
            float g00 = __bfloat162float(__ldg(&vl[(size_t)(yc0 * Wl + xc0) * CH]));
            float g01 = __bfloat162float(__ldg(&vl[(size_t)(yc0 * Wl + xc1) * CH]));
            float g10 = __bfloat162float(__ldg(&vl[(size_t)(yc1 * Wl + xc0) * CH]));
            float g11 = __bfloat162float(__ldg(&vl[(size_t)(yc1 * Wl + xc1) * CH]));

            float wp = w[l * 4 + p] * inv;
            float w00 = (1.f - lx) * (1.f - ly) * mx0 * my0 * wp;
            float w01 = lx * (1.f - ly) * mx1 * my0 * wp;
            float w10 = (1.f - lx) * ly * mx0 * my1 * wp;
            float w11 = lx * ly * mx1 * my1 * wp;

            acc += g00 * w00 + g01 * w01 + g10 * w10 + g11 * w11;
        }
    }
    out[(size_t)bq * CH + h * DHEAD + lane] = __float2bfloat16(acc);
}

// ---------------- launcher ----------------
extern "C" void kernel_launch(void* const* d_in, const int* in_sizes, int n_in,
                              void* d_out, int out_size)
{
    const float* query = (const float*)d_in[0];
    const float* value = (const float*)d_in[1];
    const float* qpos  = (const float*)d_in[2];
    const float* refp  = (const float*)d_in[3];
    const float* ln1g = (const float*)d_in[6];
    const float* ln1b = (const float*)d_in[7];
    const float* ln2g = (const float*)d_in[8];
    const float* ln2b = (const float*)d_in[9];
    const float* Wv   = (const float*)d_in[10];
    const float* bv   = (const float*)d_in[11];
    const float* Woff = (const float*)d_in[12];
    const float* boff = (const float*)d_in[13];
    const float* Wat  = (const float*)d_in[14];
    const float* bat  = (const float*)d_in[15];
    const float* Wo   = (const float*)d_in[16];
    const float* bo   = (const float*)d_in[17];
    const float* W1   = (const float*)d_in[18];
    const float* b1   = (const float*)d_in[19];
    const float* W2   = (const float*)d_in[20];
    const float* b2   = (const float*)d_in[21];
    float* out = (float*)d_out;

    __nv_bfloat16 *qb, *vbf, *vp, *sampb, *hb, *hidb;
    __nv_bfloat16 *WvT, *WoaT, *WoT, *W1T, *W2T;
    float *oa, *x, *boa;
    cudaGetSymbolAddress((void**)&qb,    g_qb);
    cudaGetSymbolAddress((void**)&vbf,   g_vb);
    cudaGetSymbolAddress((void**)&vp,    g_vp);
    cudaGetSymbolAddress((void**)&oa,    g_oa);
    cudaGetSymbolAddress((void**)&sampb, g_sampb);
    cudaGetSymbolAddress((void**)&x,     g_x);
    cudaGetSymbolAddress((void**)&hb,    g_hb);
    cudaGetSymbolAddress((void**)&hidb,  g_hidb);
    cudaGetSymbolAddress((void**)&WvT,   g_WvT);
    cudaGetSymbolAddress((void**)&WoaT,  g_WoaT);
    cudaGetSymbolAddress((void**)&WoT,   g_WoT);
    cudaGetSymbolAddress((void**)&W1T,   g_W1T);
    cudaGetSymbolAddress((void**)&W2T,   g_W2T);
    cudaGetSymbolAddress((void**)&boa,   g_boa);

    auto ggrid = [](int M, int N) { return dim3((N + 127) / 128, (M + 127) / 128); };

    wconv_all<<<(WCONV_TOTAL + 255) / 256, 256>>>(Wv, Woff, Wat, Wo, W1, W2, boff, bat);
    f2b_kernel<<<(MV * CH + 255) / 256, 256>>>(value, vbf, MV * CH);
    ln_kernel<<<MQ, 256>>>(query, ln1g, ln1b, qpos, qb);
    hgemm_kernel<3><<<ggrid(MV, CH), 256>>>(vbf, WvT, bv, nullptr, nullptr, vp, MV, CH, CH);
    hgemm_kernel<0><<<ggrid(MQ, NOA), 256>>>(qb, WoaT, boa, nullptr, oa, nullptr, MQ, NOA, CH);
    sample_kernel<<<MQ, 256>>>(oa, refp, vp, sampb);
    hgemm_kernel<1><<<ggrid(MQ, CH), 256>>>(sampb, WoT, bo, query, x, nullptr, MQ, CH, CH);
    ln_kernel<<<MQ, 256>>>(x, ln2g, ln2b, nullptr, hb);
    hgemm_kernel<2><<<ggrid(MQ, FFN), 256>>>(hb, W1T, b1, nullptr, nullptr, hidb, MQ, FFN, CH);
    hgemm_kernel<1><<<ggrid(MQ, CH), 256>>>(hidb, W2T, b2, x, out, nullptr, MQ, CH, FFN);
}

// round 10
// speedup vs baseline: 5.3757x; 1.6524x over previous
#include <cuda_runtime.h>
#include <cuda_bf16.h>
#include <math.h>
#include <stdint.h>

// ---------------- problem constants ----------------
#define BATCH 2
#define QLEN  16384
#define CH    256
#define HEADS 8
#define DHEAD 32
#define NV    13125          // 100*100 + 50*50 + 25*25
#define NOA   288            // 192 offsets + 96 attn logits
#define FFN   1024
#define MQ    (BATCH*QLEN)   // 32768
#define MV    (BATCH*NV)     // 26250

// ---------------- scratch (allocation-free) ----------------
__device__ __nv_bfloat16 g_qb  [MQ*CH];
__device__ __nv_bfloat16 g_vb  [MV*CH];
__device__ __nv_bfloat16 g_vp  [MV*CH];
__device__ float         g_oa  [MQ*NOA];
__device__ __nv_bfloat16 g_sampb[MQ*CH];
__device__ float         g_x   [MQ*CH];
__device__ __nv_bfloat16 g_hb  [MQ*CH];
__device__ __nv_bfloat16 g_hidb[MQ*FFN];

__device__ __nv_bfloat16 g_WvT [CH*CH];
__device__ __nv_bfloat16 g_WoaT[NOA*CH];
__device__ __nv_bfloat16 g_WoT [CH*CH];
__device__ __nv_bfloat16 g_W1T [FFN*CH];
__device__ __nv_bfloat16 g_W2T [CH*FFN];
__device__ float         g_boa [NOA];

// ---------------- helpers ----------------
__device__ __forceinline__ float gelu_f(float x) {
    return 0.5f * x * (1.0f + erff(x * 0.70710678118654752f));
}
__device__ __forceinline__ void cp_async16(uint32_t dst, const void* src, int sz) {
    asm volatile("cp.async.cg.shared.global [%0], [%1], 16, %2;\n"
                 :: "r"(dst), "l"(src), "r"(sz));
}
__device__ __forceinline__ void cp_commit() { asm volatile("cp.async.commit_group;\n"); }
__device__ __forceinline__ void ldsm_x4(uint32_t& r0, uint32_t& r1, uint32_t& r2, uint32_t& r3,
                                        uint32_t addr) {
    asm volatile("ldmatrix.sync.aligned.m8n8.x4.shared.b16 {%0,%1,%2,%3}, [%4];\n"
                 : "=r"(r0), "=r"(r1), "=r"(r2), "=r"(r3) : "r"(addr));
}
__device__ __forceinline__ void mma_bf16(float* c, uint32_t a0, uint32_t a1, uint32_t a2,
                                         uint32_t a3, uint32_t b0, uint32_t b1) {
    asm volatile("mma.sync.aligned.m16n8k16.row.col.f32.bf16.bf16.f32 "
                 "{%0,%1,%2,%3}, {%4,%5,%6,%7}, {%8,%9}, {%0,%1,%2,%3};\n"
                 : "+f"(c[0]), "+f"(c[1]), "+f"(c[2]), "+f"(c[3])
                 : "r"(a0), "r"(a1), "r"(a2), "r"(a3), "r"(b0), "r"(b1));
}

// ---------------- all weight transposes + concat in ONE kernel ----------------
__global__ void wconv_all(const float* __restrict__ Wv, const float* __restrict__ Woff,
                          const float* __restrict__ Wat, const float* __restrict__ Wo,
                          const float* __restrict__ W1, const float* __restrict__ W2,
                          const float* __restrict__ boff, const float* __restrict__ bat)
{
    int idx = blockIdx.x * 256 + threadIdx.x;
    if (idx < 65536) {
        int n = idx >> 8, k = idx & 255;
        g_WvT[idx] = __float2bfloat16(Wv[k * CH + n]);
        return;
    }
    idx -= 65536;
    if (idx < 73728) {
        int n = idx >> 8, k = idx & 255;
        float w = (n < 192) ? Woff[k * 192 + n] : Wat[k * 96 + (n - 192)];
        g_WoaT[idx] = __float2bfloat16(w);
        return;
    }
    idx -= 73728;
    if (idx < 65536) {
        int n = idx >> 8, k = idx & 255;
        g_WoT[idx] = __float2bfloat16(Wo[k * CH + n]);
        return;
    }
    idx -= 65536;
    if (idx < 262144) {
        int n = idx >> 8, k = idx & 255;
        g_W1T[idx] = __float2bfloat16(W1[k * FFN + n]);
        return;
    }
    idx -= 262144;
    if (idx < 262144) {
        int n = idx >> 10, k = idx & 1023;
        g_W2T[idx] = __float2bfloat16(W2[k * CH + n]);
        return;
    }
    idx -= 262144;
    if (idx < NOA) g_boa[idx] = (idx < 192) ? boff[idx] : bat[idx - 192];
}
#define WCONV_TOTAL (65536 + 73728 + 65536 + 262144 + 262144 + NOA)

// ---------------- fp32 -> bf16 elementwise ----------------
__global__ void f2b_kernel(const float* __restrict__ in, __nv_bfloat16* __restrict__ out, int n) {
    int idx = blockIdx.x * 256 + threadIdx.x;
    if (idx < n) out[idx] = __float2bfloat16(in[idx]);
}

// ---------------- LayerNorm -> bf16 : one warp per row, shuffle reduce --------
__global__ void ln_kernel(const float* __restrict__ x,
                          const float* __restrict__ g,
                          const float* __restrict__ b,
                          const float* __restrict__ add,
                          __nv_bfloat16* __restrict__ out)
{
    int warp = threadIdx.x >> 5;
    int lane = threadIdx.x & 31;
    int row  = blockIdx.x * 8 + warp;

    const float4* xr = (const float4*)(x + (size_t)row * CH);
    float4 v0 = xr[lane];
    float4 v1 = xr[lane + 32];

    float s = v0.x + v0.y + v0.z + v0.w + v1.x + v1.y + v1.z + v1.w;
    #pragma unroll
    for (int o = 16; o > 0; o >>= 1) s += __shfl_xor_sync(0xffffffffu, s, o);
    float mean = s * (1.0f / CH);

    float d0x = v0.x - mean, d0y = v0.y - mean, d0z = v0.z - mean, d0w = v0.w - mean;
    float d1x = v1.x - mean, d1y = v1.y - mean, d1z = v1.z - mean, d1w = v1.w - mean;
    float q = d0x*d0x + d0y*d0y + d0z*d0z + d0w*d0w + d1x*d1x + d1y*d1y + d1z*d1z + d1w*d1w;
    #pragma unroll
    for (int o = 16; o > 0; o >>= 1) q += __shfl_xor_sync(0xffffffffu, q, o);
    float rstd = rsqrtf(q * (1.0f / CH) + 1e-5f);

    const float4* gp = (const float4*)g;
    const float4* bp = (const float4*)b;
    float4 g0 = gp[lane], g1 = gp[lane + 32];
    float4 b0 = bp[lane], b1 = bp[lane + 32];

    float y0x = d0x * rstd * g0.x + b0.x;
    float y0y = d0y * rstd * g0.y + b0.y;
    float y0z = d0z * rstd * g0.z + b0.z;
    float y0w = d0w * rstd * g0.w + b0.w;
    float y1x = d1x * rstd * g1.x + b1.x;
    float y1y = d1y * rstd * g1.y + b1.y;
    float y1z = d1z * rstd * g1.z + b1.z;
    float y1w = d1w * rstd * g1.w + b1.w;

    if (add) {
        const float4* ar = (const float4*)(add + (size_t)row * CH);
        float4 a0 = ar[lane], a1 = ar[lane + 32];
        y0x += a0.x; y0y += a0.y; y0z += a0.z; y0w += a0.w;
        y1x += a1.x; y1y += a1.y; y1z += a1.z; y1w += a1.w;
    }

    __nv_bfloat16* orow = out + (size_t)row * CH;
    __nv_bfloat162 p0 = {__float2bfloat16(y0x), __float2bfloat16(y0y)};
    __nv_bfloat162 p1 = {__float2bfloat16(y0z), __float2bfloat16(y0w)};
    __nv_bfloat162 p2 = {__float2bfloat16(y1x), __float2bfloat16(y1y)};
    __nv_bfloat162 p3 = {__float2bfloat16(y1z), __float2bfloat16(y1w)};
    ((uint2*)orow)[lane]      = make_uint2(*(uint32_t*)&p0, *(uint32_t*)&p1);
    ((uint2*)orow)[lane + 32] = make_uint2(*(uint32_t*)&p2, *(uint32_t*)&p3);
}

// ---------------- bf16 HMMA GEMM 128x128x32, 3-stage cp.async pipeline --------
// EPI 0: fp32=acc+bias ; 1: fp32=acc+bias+res ; 2: bf16=gelu(acc+bias) ; 3: bf16=acc+bias
#define LDSM_PAD 40
#define A_ELEMS (128 * LDSM_PAD)
#define B_ELEMS (128 * LDSM_PAD)
#define STAGES  3

template<int EPI>
__global__ void __launch_bounds__(256, 2)
hgemm_kernel(const __nv_bfloat16* __restrict__ A,
             const __nv_bfloat16* __restrict__ Bt,
             const float* __restrict__ bias,
             const float* __restrict__ res,
             float* __restrict__ Cf,
             __nv_bfloat16* __restrict__ Cb,
             int M, int N, int K)
{
    __shared__ __nv_bfloat16 As[STAGES][A_ELEMS];
    __shared__ __nv_bfloat16 Bs[STAGES][B_ELEMS];

    const int tid  = threadIdx.x;
    const int lane = tid & 31;
    const int warp = tid >> 5;
    const int wm   = warp >> 2;
    const int wn   = warp & 3;
    const int bm   = blockIdx.y * 128;
    const int bn   = blockIdx.x * 128;

    const uint32_t asBase = (uint32_t)__cvta_generic_to_shared(&As[0][0]);
    const uint32_t bsBase = (uint32_t)__cvta_generic_to_shared(&Bs[0][0]);

    const int row0 = tid >> 2;
    const int c8   = (tid & 3) * 8;

    float acc[4][4][4];
    #pragma unroll
    for (int i = 0; i < 4; i++)
        #pragma unroll
        for (int j = 0; j < 4; j++)
            #pragma unroll
            for (int r = 0; r < 4; r++) acc[i][j][r] = 0.f;

    const int KT = K >> 5;

    auto issue = [&](int kt, int buf) {
        #pragma unroll
        for (int i = 0; i < 2; i++) {
            int row = row0 + i * 64;
            int gm  = bm + row;
            const __nv_bfloat16* src = A + (size_t)(gm < M ? gm : M - 1) * K + kt * 32 + c8;
            cp_async16(asBase + (uint32_t)(buf * A_ELEMS + row * LDSM_PAD + c8) * 2,
                       src, gm < M ? 16 : 0);
        }
        #pragma unroll
        for (int i = 0; i < 2; i++) {
            int row = row0 + i * 64;
            int gn  = bn + row;
            const __nv_bfloat16* src = Bt + (size_t)(gn < N ? gn : N - 1) * K + kt * 32 + c8;
            cp_async16(bsBase + (uint32_t)(buf * B_ELEMS + row * LDSM_PAD + c8) * 2,
                       src, gn < N ? 16 : 0);
        }
        cp_commit();
    };

    issue(0, 0);
    if (KT > 1) issue(1, 1);

    int buf = 0;
    int nxt = (KT > 2) ? 2 : 0;

    for (int kt = 0; kt < KT; kt++) {
        if (kt + 1 < KT) asm volatile("cp.async.wait_group 1;\n");
        else             asm volatile("cp.async.wait_group 0;\n");
        __syncthreads();

        if (kt + 2 < KT) issue(kt + 2, nxt);

        const uint32_t aB = asBase + (uint32_t)(buf * A_ELEMS) * 2;
        const uint32_t bB = bsBase + (uint32_t)(buf * B_ELEMS) * 2;

        #pragma unroll
        for (int ks = 0; ks < 2; ks++) {
            uint32_t a[4][4];
            #pragma unroll
            for (int mt = 0; mt < 4; mt++) {
                uint32_t addr = aB + (uint32_t)((wm * 64 + mt * 16 + (lane & 15)) * LDSM_PAD
                                                + ks * 16 + (lane >> 4) * 8) * 2;
                ldsm_x4(a[mt][0], a[mt][1], a[mt][2], a[mt][3], addr);
            }
            uint32_t b[4][2];
            #pragma unroll
            for (int np = 0; np < 2; np++) {
                int g = lane >> 3;
                uint32_t addr = bB + (uint32_t)((wn * 32 + np * 16 + (g >> 1) * 8 + (lane & 7)) * LDSM_PAD
                                                + ks * 16 + (g & 1) * 8) * 2;
                uint32_t r0, r1, r2, r3;
                ldsm_x4(r0, r1, r2, r3, addr);
                b[np * 2 + 0][0] = r0; b[np * 2 + 0][1] = r1;
                b[np * 2 + 1][0] = r2; b[np * 2 + 1][1] = r3;
            }
            #pragma unroll
            for (int mt = 0; mt < 4; mt++)
                #pragma unroll
                for (int nt = 0; nt < 4; nt++)
                    mma_bf16(acc[mt][nt], a[mt][0], a[mt][1], a[mt][2], a[mt][3],
                             b[nt][0], b[nt][1]);
        }

        buf = (buf + 1 == STAGES) ? 0 : buf + 1;
        nxt = (nxt + 1 == STAGES) ? 0 : nxt + 1;
    }

    #pragma unroll
    for (int mt = 0; mt < 4; mt++) {
        #pragma unroll
        for (int nt = 0; nt < 4; nt++) {
            int m0 = bm + wm * 64 + mt * 16 + (lane >> 2);
            int n0 = bn + wn * 32 + nt * 8 + (lane & 3) * 2;
            #pragma unroll
            for (int half = 0; half < 2; half++) {
                int gm = m0 + half * 8;
                if (gm >= M) continue;
                #pragma unroll
                for (int c = 0; c < 2; c++) {
                    int gn = n0 + c;
                    if (gn >= N) continue;
                    float v = acc[mt][nt][half * 2 + c] + bias[gn];
                    if (EPI == 1) v += res[(size_t)gm * N + gn];
                    if (EPI == 2) Cb[(size_t)gm * N + gn] = __float2bfloat16(gelu_f(v));
                    else if (EPI == 3) Cb[(size_t)gm * N + gn] = __float2bfloat16(v);
                    else Cf[(size_t)gm * N + gn] = v;
                }
            }
        }
    }
}

// ---------------- deformable sampling: 4 heads per warp, uint2 gathers --------
// lane group g = lane>>3 handles head hbase+g; (lane&7)*4 = channel quad.
__global__ void sample_kernel(const float* __restrict__ oa,
                              const float* __restrict__ refp,
                              const __nv_bfloat16* __restrict__ v,
                              __nv_bfloat16* __restrict__ out)
{
    int gwarp = blockIdx.x * 8 + (threadIdx.x >> 5);  // global warp id
    int bq    = gwarp >> 1;                            // (b*Q+q)
    int hbase = (gwarp & 1) * 4;
    int lane  = threadIdx.x & 31;
    int g     = lane >> 3;                             // head within warp
    int h     = hbase + g;
    int c4    = (lane & 7) * 4;                        // channel quad start

    // softmax over this head's 12 logits (redundant across the 8 lanes of a group)
    const float* lg = oa + (size_t)bq * NOA + 192 + h * 12;
    float w[12];
    float mx = -1e30f;
    #pragma unroll
    for (int i = 0; i < 12; i++) { w[i] = lg[i]; mx = fmaxf(mx, w[i]); }
    float s = 0.f;
    #pragma unroll
    for (int i = 0; i < 12; i++) { w[i] = __expf(w[i] - mx); s += w[i]; }
    float inv = 1.f / s;

    float rx = refp[(size_t)bq * 2 + 0];
    float ry = refp[(size_t)bq * 2 + 1];

    const float* offp = oa + (size_t)bq * NOA + h * 24;
    int b = bq >> 14;
    const __nv_bfloat16* vb = v + ((size_t)b * NV) * CH + h * DHEAD + c4;

    const int HsA[3]    = {100, 50, 25};
    const int startA[3] = {0, 10000, 12500};

    float a0 = 0.f, a1 = 0.f, a2 = 0.f, a3 = 0.f;
    #pragma unroll
    for (int l = 0; l < 3; l++) {
        const int Wl = HsA[l];
        const float fW = (float)Wl;
        const __nv_bfloat16* vl = vb + (size_t)startA[l] * CH;
        #pragma unroll
        for (int p = 0; p < 4; p++) {
            float ox = offp[(l * 4 + p) * 2 + 0];
            float oy = offp[(l * 4 + p) * 2 + 1];
            float x = (rx + ox / fW) * fW - 0.5f;
            float y = (ry + oy / fW) * fW - 0.5f;
            float x0f = floorf(x), y0f = floorf(y);
            float lx = x - x0f, ly = y - y0f;
            int x0 = (int)x0f, y0 = (int)y0f;

            float mx0 = (x0 >= 0     && x0 < Wl)     ? 1.f : 0.f;
            float mx1 = (x0 + 1 >= 0 && x0 + 1 < Wl) ? 1.f : 0.f;
            float my0 = (y0 >= 0     && y0 < Wl)     ? 1.f : 0.f;
            float my1 = (y0 + 1 >= 0 && y0 + 1 < Wl) ? 1.f : 0.f;

            int xc0 = min(max(x0, 0), Wl - 1);
            int xc1 = min(max(x0 + 1, 0), Wl - 1);
            int yc0 = min(max(y0, 0), Wl - 1);
            int yc1 = min(max(y0 + 1, 0), Wl - 1);

            uint2 q00 = __ldg((const uint2*)(vl + (size_t)(yc0 * Wl + xc0) * CH));
            uint2 q01 = __ldg((const uint2*)(vl + (size_t)(yc0 * Wl + xc1) * CH));
            uint2 q10 = __ldg((const uint2*)(vl + (size_t)(yc1 * Wl + xc0) * CH));
            uint2 q11 = __ldg((const uint2*)(vl + (size_t)(yc1 * Wl + xc1) * CH));

            float wp  = w[l * 4 + p] * inv;
            float w00 = (1.f - lx) * (1.f - ly) * mx0 * my0 * wp;
            float w01 = lx * (1.f - ly) * mx1 * my0 * wp;
            float w10 = (1.f - lx) * ly * mx0 * my1 * wp;
            float w11 = lx * ly * mx1 * my1 * wp;

            float2 f;
            f = __bfloat1622float2(*(__nv_bfloat162*)&q00.x); a0 += f.x * w00; a1 += f.y * w00;
            f = __bfloat1622float2(*(__nv_bfloat162*)&q00.y); a2 += f.x * w00; a3 += f.y * w00;
            f = __bfloat1622float2(*(__nv_bfloat162*)&q01.x); a0 += f.x * w01; a1 += f.y * w01;
            f = __bfloat1622float2(*(__nv_bfloat162*)&q01.y); a2 += f.x * w01; a3 += f.y * w01;
            f = __bfloat1622float2(*(__nv_bfloat162*)&q10.x); a0 += f.x * w10; a1 += f.y * w10;
            f = __bfloat1622float2(*(__nv_bfloat162*)&q10.y); a2 += f.x * w10; a3 += f.y * w10;
            f = __bfloat1622float2(*(__nv_bfloat162*)&q11.x); a0 += f.x * w11; a1 += f.y * w11;
            f = __bfloat1622float2(*(__nv_bfloat162*)&q11.y); a2 += f.x * w11; a3 += f.y * w11;
        }
    }

    __nv_bfloat162 o0 = {__float2bfloat16(a0), __float2bfloat16(a1)};
    __nv_bfloat162 o1 = {__float2bfloat16(a2), __float2bfloat16(a3)};
    *(uint2*)(out + (size_t)bq * CH + h * DHEAD + c4) =
        make_uint2(*(uint32_t*)&o0, *(uint32_t*)&o1);
}

// ---------------- launcher ----------------
extern "C" void kernel_launch(void* const* d_in, const int* in_sizes, int n_in,
                              void* d_out, int out_size)
{
    const float* query = (const float*)d_in[0];
    const float* value = (const float*)d_in[1];
    const float* qpos  = (const float*)d_in[2];
    const float* refp  = (const float*)d_in[3];
    const float* ln1g = (const float*)d_in[6];
    const float* ln1b = (const float*)d_in[7];
    const float* ln2g = (const float*)d_in[8];
    const float* ln2b = (const float*)d_in[9];
    const float* Wv   = (const float*)d_in[10];
    const float* bv   = (const float*)d_in[11];
    const float* Woff = (const float*)d_in[12];
    const float* boff = (const float*)d_in[13];
    const float* Wat  = (const float*)d_in[14];
    const float* bat  = (const float*)d_in[15];
    const float* Wo   = (const float*)d_in[16];
    const float* bo   = (const float*)d_in[17];
    const float* W1   = (const float*)d_in[18];
    const float* b1   = (const float*)d_in[19];
    const float* W2   = (const float*)d_in[20];
    const float* b2   = (const float*)d_in[21];
    float* out = (float*)d_out;

    __nv_bfloat16 *qb, *vbf, *vp, *sampb, *hb, *hidb;
    __nv_bfloat16 *WvT, *WoaT, *WoT, *W1T, *W2T;
    float *oa, *x, *boa;
    cudaGetSymbolAddress((void**)&qb,    g_qb);
    cudaGetSymbolAddress((void**)&vbf,   g_vb);
    cudaGetSymbolAddress((void**)&vp,    g_vp);
    cudaGetSymbolAddress((void**)&oa,    g_oa);
    cudaGetSymbolAddress((void**)&sampb, g_sampb);
    cudaGetSymbolAddress((void**)&x,     g_x);
    cudaGetSymbolAddress((void**)&hb,    g_hb);
    cudaGetSymbolAddress((void**)&hidb,  g_hidb);
    cudaGetSymbolAddress((void**)&WvT,   g_WvT);
    cudaGetSymbolAddress((void**)&WoaT,  g_WoaT);
    cudaGetSymbolAddress((void**)&WoT,   g_WoT);
    cudaGetSymbolAddress((void**)&W1T,   g_W1T);
    cudaGetSymbolAddress((void**)&W2T,   g_W2T);
    cudaGetSymbolAddress((void**)&boa,   g_boa);

    auto ggrid = [](int M, int N) { return dim3((N + 127) / 128, (M + 127) / 128); };

    wconv_all<<<(WCONV_TOTAL + 255) / 256, 256>>>(Wv, Woff, Wat, Wo, W1, W2, boff, bat);
    f2b_kernel<<<(MV * CH + 255) / 256, 256>>>(value, vbf, MV * CH);
    ln_kernel<<<MQ / 8, 256>>>(query, ln1g, ln1b, qpos, qb);
    hgemm_kernel<3><<<ggrid(MV, CH), 256>>>(vbf, WvT, bv, nullptr, nullptr, vp, MV, CH, CH);
    hgemm_kernel<0><<<ggrid(MQ, NOA), 256>>>(qb, WoaT, boa, nullptr, oa, nullptr, MQ, NOA, CH);
    sample_kernel<<<MQ / 4, 256>>>(oa, refp, vp, sampb);
    hgemm_kernel<1><<<ggrid(MQ, CH), 256>>>(sampb, WoT, bo, query, x, nullptr, MQ, CH, CH);
    ln_kernel<<<MQ / 8, 256>>>(x, ln2g, ln2b, nullptr, hb);
    hgemm_kernel<2><<<ggrid(MQ, FFN), 256>>>(hb, W1T, b1, nullptr, nullptr, hidb, MQ, FFN, CH);
    hgemm_kernel<1><<<ggrid(MQ, CH), 256>>>(hidb, W2T, b2, x, out, nullptr, MQ, CH, FFN);
}

// round 13
// speedup vs baseline: 5.6500x; 1.0510x over previous
#include <cuda_runtime.h>
#include <cuda_bf16.h>
#include <math.h>
#include <stdint.h>

// ---------------- problem constants ----------------
#define BATCH 2
#define QLEN  16384
#define CH    256
#define HEADS 8
#define DHEAD 32
#define NV    13125          // 100*100 + 50*50 + 25*25
#define NOA   288            // 192 offsets + 96 attn logits
#define FFN   1024
#define MQ    (BATCH*QLEN)   // 32768
#define MV    (BATCH*NV)     // 26250

// ---------------- scratch (allocation-free) ----------------
__device__ __nv_bfloat16 g_qb  [MQ*CH];
__device__ __nv_bfloat16 g_vb  [MV*CH];
__device__ __nv_bfloat16 g_vp  [MV*CH];
__device__ float         g_oa  [MQ*NOA];
__device__ __nv_bfloat16 g_sampb[MQ*CH];
__device__ float         g_x   [MQ*CH];
__device__ __nv_bfloat16 g_hb  [MQ*CH];
__device__ __nv_bfloat16 g_hidb[MQ*FFN];

__device__ __nv_bfloat16 g_WvT [CH*CH];
__device__ __nv_bfloat16 g_WoaT[NOA*CH];
__device__ __nv_bfloat16 g_WoT [CH*CH];
__device__ __nv_bfloat16 g_W1T [FFN*CH];
__device__ __nv_bfloat16 g_W2T [CH*FFN];
__device__ float         g_boa [NOA];

// ---------------- helpers ----------------
__device__ __forceinline__ float gelu_f(float x) {
    return 0.5f * x * (1.0f + erff(x * 0.70710678118654752f));
}
__device__ __forceinline__ void cp_async16(uint32_t dst, const void* src, int sz) {
    asm volatile("cp.async.cg.shared.global [%0], [%1], 16, %2;\n"
                 :: "r"(dst), "l"(src), "r"(sz));
}
__device__ __forceinline__ void cp_commit() { asm volatile("cp.async.commit_group;\n"); }
__device__ __forceinline__ void ldsm_x4(uint32_t& r0, uint32_t& r1, uint32_t& r2, uint32_t& r3,
                                        uint32_t addr) {
    asm volatile("ldmatrix.sync.aligned.m8n8.x4.shared.b16 {%0,%1,%2,%3}, [%4];\n"
                 : "=r"(r0), "=r"(r1), "=r"(r2), "=r"(r3) : "r"(addr));
}
__device__ __forceinline__ void mma_bf16(float* c, uint32_t a0, uint32_t a1, uint32_t a2,
                                         uint32_t a3, uint32_t b0, uint32_t b1) {
    asm volatile("mma.sync.aligned.m16n8k16.row.col.f32.bf16.bf16.f32 "
                 "{%0,%1,%2,%3}, {%4,%5,%6,%7}, {%8,%9}, {%0,%1,%2,%3};\n"
                 : "+f"(c[0]), "+f"(c[1]), "+f"(c[2]), "+f"(c[3])
                 : "r"(a0), "r"(a1), "r"(a2), "r"(a3), "r"(b0), "r"(b1));
}
#define SWZ128(o) ((o) ^ (((o) >> 3) & 0x70))

// ---------------- all weight transposes + concat in ONE kernel ----------------
__global__ void wconv_all(const float* __restrict__ Wv, const float* __restrict__ Woff,
                          const float* __restrict__ Wat, const float* __restrict__ Wo,
                          const float* __restrict__ W1, const float* __restrict__ W2,
                          const float* __restrict__ boff, const float* __restrict__ bat)
{
    int idx = blockIdx.x * 256 + threadIdx.x;
    if (idx < 65536) {
        int n = idx >> 8, k = idx & 255;
        g_WvT[idx] = __float2bfloat16(Wv[k * CH + n]);
        return;
    }
    idx -= 65536;
    if (idx < 73728) {
        int n = idx >> 8, k = idx & 255;
        float w = (n < 192) ? Woff[k * 192 + n] : Wat[k * 96 + (n - 192)];
        g_WoaT[idx] = __float2bfloat16(w);
        return;
    }
    idx -= 73728;
    if (idx < 65536) {
        int n = idx >> 8, k = idx & 255;
        g_WoT[idx] = __float2bfloat16(Wo[k * CH + n]);
        return;
    }
    idx -= 65536;
    if (idx < 262144) {
        int n = idx >> 8, k = idx & 255;
        g_W1T[idx] = __float2bfloat16(W1[k * FFN + n]);
        return;
    }
    idx -= 262144;
    if (idx < 262144) {
        int n = idx >> 10, k = idx & 1023;
        g_W2T[idx] = __float2bfloat16(W2[k * CH + n]);
        return;
    }
    idx -= 262144;
    if (idx < NOA) g_boa[idx] = (idx < 192) ? boff[idx] : bat[idx - 192];
}
#define WCONV_TOTAL (65536 + 73728 + 65536 + 262144 + 262144 + NOA)

// ---------------- fp32 -> bf16 elementwise ----------------
__global__ void f2b_kernel(const float* __restrict__ in, __nv_bfloat16* __restrict__ out, int n) {
    int idx = blockIdx.x * 256 + threadIdx.x;
    if (idx < n) out[idx] = __float2bfloat16(in[idx]);
}

// ---------------- LayerNorm -> bf16 : one warp per row, shuffle reduce --------
__global__ void ln_kernel(const float* __restrict__ x,
                          const float* __restrict__ g,
                          const float* __restrict__ b,
                          const float* __restrict__ add,
                          __nv_bfloat16* __restrict__ out)
{
    int warp = threadIdx.x >> 5;
    int lane = threadIdx.x & 31;
    int row  = blockIdx.x * 8 + warp;

    const float4* xr = (const float4*)(x + (size_t)row * CH);
    float4 v0 = xr[lane];
    float4 v1 = xr[lane + 32];

    float s = v0.x + v0.y + v0.z + v0.w + v1.x + v1.y + v1.z + v1.w;
    #pragma unroll
    for (int o = 16; o > 0; o >>= 1) s += __shfl_xor_sync(0xffffffffu, s, o);
    float mean = s * (1.0f / CH);

    float d0x = v0.x - mean, d0y = v0.y - mean, d0z = v0.z - mean, d0w = v0.w - mean;
    float d1x = v1.x - mean, d1y = v1.y - mean, d1z = v1.z - mean, d1w = v1.w - mean;
    float q = d0x*d0x + d0y*d0y + d0z*d0z + d0w*d0w + d1x*d1x + d1y*d1y + d1z*d1z + d1w*d1w;
    #pragma unroll
    for (int o = 16; o > 0; o >>= 1) q += __shfl_xor_sync(0xffffffffu, q, o);
    float rstd = rsqrtf(q * (1.0f / CH) + 1e-5f);

    const float4* gp = (const float4*)g;
    const float4* bp = (const float4*)b;
    float4 g0 = gp[lane], g1 = gp[lane + 32];
    float4 b0 = bp[lane], b1 = bp[lane + 32];

    float y0x = d0x * rstd * g0.x + b0.x;
    float y0y = d0y * rstd * g0.y + b0.y;
    float y0z = d0z * rstd * g0.z + b0.z;
    float y0w = d0w * rstd * g0.w + b0.w;
    float y1x = d1x * rstd * g1.x + b1.x;
    float y1y = d1y * rstd * g1.y + b1.y;
    float y1z = d1z * rstd * g1.z + b1.z;
    float y1w = d1w * rstd * g1.w + b1.w;

    if (add) {
        const float4* ar = (const float4*)(add + (size_t)row * CH);
        float4 a0 = ar[lane], a1 = ar[lane + 32];
        y0x += a0.x; y0y += a0.y; y0z += a0.z; y0w += a0.w;
        y1x += a1.x; y1y += a1.y; y1z += a1.z; y1w += a1.w;
    }

    __nv_bfloat16* orow = out + (size_t)row * CH;
    __nv_bfloat162 p0 = {__float2bfloat16(y0x), __float2bfloat16(y0y)};
    __nv_bfloat162 p1 = {__float2bfloat16(y0z), __float2bfloat16(y0w)};
    __nv_bfloat162 p2 = {__float2bfloat16(y1x), __float2bfloat16(y1y)};
    __nv_bfloat162 p3 = {__float2bfloat16(y1z), __float2bfloat16(y1w)};
    ((uint2*)orow)[lane]      = make_uint2(*(uint32_t*)&p0, *(uint32_t*)&p1);
    ((uint2*)orow)[lane + 32] = make_uint2(*(uint32_t*)&p2, *(uint32_t*)&p3);
}

// ---------------- bf16 HMMA GEMM 128x128, K-chunks of 64, canonical SW128 -----
// Smem tile: 128 rows x 128B (K64 bf16), XOR-swizzled -> conflict-free for both
// cp.async 16B writes and ldmatrix reads. 3-stage pipeline, one sync per chunk.
// EPI 0: fp32=acc+bias ; 1: fp32=acc+bias+res ; 2: bf16=gelu(acc+bias) ; 3: bf16=acc+bias
#define KC        64
#define TILE_B    16384                   // 128 rows * 128 bytes
#define STAGE_B   (2 * TILE_B)            // A tile + B tile
#define STAGES    3
#define GSMEM     (STAGES * STAGE_B)      // 98304 bytes

template<int EPI>
__global__ void __launch_bounds__(256, 2)
hgemm_kernel(const __nv_bfloat16* __restrict__ A,
             const __nv_bfloat16* __restrict__ Bt,
             const float* __restrict__ bias,
             const float* __restrict__ res,
             float* __restrict__ Cf,
             __nv_bfloat16* __restrict__ Cb,
             int M, int N, int K)
{
    extern __shared__ char dsmem[];
    const uint32_t sb = (uint32_t)__cvta_generic_to_shared(dsmem);

    const int tid  = threadIdx.x;
    const int lane = tid & 31;
    const int warp = tid >> 5;
    const int wm   = warp >> 2;   // 0..1 : 64 rows
    const int wn   = warp & 3;    // 0..3 : 32 cols
    const int bm   = blockIdx.y * 128;
    const int bn   = blockIdx.x * 128;

    float acc[4][4][4];
    #pragma unroll
    for (int i = 0; i < 4; i++)
        #pragma unroll
        for (int j = 0; j < 4; j++)
            #pragma unroll
            for (int r = 0; r < 4; r++) acc[i][j][r] = 0.f;

    const int KT = K >> 6;   // K / 64

    auto issue = [&](int kt, int st) {
        const uint32_t dA = sb + (uint32_t)st * STAGE_B;
        const uint32_t dB = dA + TILE_B;
        const int kc = kt * KC;
        #pragma unroll
        for (int i = 0; i < 4; i++) {
            int slot = tid + i * 256;            // 0..1023
            int row  = slot >> 3;                // 0..127
            int colb = (slot & 7) * 16;          // 0..112 (bytes)
            uint32_t so = SWZ128((uint32_t)(row * 128 + colb));
            int gm = bm + row;
            cp_async16(dA + so, A + (size_t)(gm < M ? gm : M - 1) * K + kc + (colb >> 1),
                       gm < M ? 16 : 0);
            int gn = bn + row;
            cp_async16(dB + so, Bt + (size_t)(gn < N ? gn : N - 1) * K + kc + (colb >> 1),
                       gn < N ? 16 : 0);
        }
        cp_commit();
    };

    issue(0, 0);
    if (KT > 1) issue(1, 1);

    int buf = 0;
    int nxt = (KT > 2) ? 2 : 0;

    for (int kt = 0; kt < KT; kt++) {
        if (kt + 1 < KT) asm volatile("cp.async.wait_group 1;\n");
        else             asm volatile("cp.async.wait_group 0;\n");
        __syncthreads();

        if (kt + 2 < KT) issue(kt + 2, nxt);

        const uint32_t aB = sb + (uint32_t)buf * STAGE_B;
        const uint32_t bB = aB + TILE_B;

        #pragma unroll
        for (int ks = 0; ks < 4; ks++) {          // 4 x K16 per chunk
            uint32_t a[4][4];
            #pragma unroll
            for (int mt = 0; mt < 4; mt++) {
                int row  = wm * 64 + mt * 16 + (lane & 15);
                int colb = ks * 32 + (lane >> 4) * 16;
                ldsm_x4(a[mt][0], a[mt][1], a[mt][2], a[mt][3],
                        aB + SWZ128((uint32_t)(row * 128 + colb)));
            }
            uint32_t b[4][2];
            #pragma unroll
            for (int np = 0; np < 2; np++) {
                int g    = lane >> 3;
                int row  = wn * 32 + np * 16 + (g >> 1) * 8 + (lane & 7);
                int colb = ks * 32 + (g & 1) * 16;
                uint32_t r0, r1, r2, r3;
                ldsm_x4(r0, r1, r2, r3, bB + SWZ128((uint32_t)(row * 128 + colb)));
                b[np * 2 + 0][0] = r0; b[np * 2 + 0][1] = r1;
                b[np * 2 + 1][0] = r2; b[np * 2 + 1][1] = r3;
            }
            #pragma unroll
            for (int mt = 0; mt < 4; mt++)
                #pragma unroll
                for (int nt = 0; nt < 4; nt++)
                    mma_bf16(acc[mt][nt], a[mt][0], a[mt][1], a[mt][2], a[mt][3],
                             b[nt][0], b[nt][1]);
        }

        buf = (buf + 1 == STAGES) ? 0 : buf + 1;
        nxt = (nxt + 1 == STAGES) ? 0 : nxt + 1;
    }

    #pragma unroll
    for (int mt = 0; mt < 4; mt++) {
        #pragma unroll
        for (int nt = 0; nt < 4; nt++) {
            int m0 = bm + wm * 64 + mt * 16 + (lane >> 2);
            int n0 = bn + wn * 32 + nt * 8 + (lane & 3) * 2;
            #pragma unroll
            for (int half = 0; half < 2; half++) {
                int gm = m0 + half * 8;
                if (gm >= M) continue;
                #pragma unroll
                for (int c = 0; c < 2; c++) {
                    int gn = n0 + c;
                    if (gn >= N) continue;
                    float v = acc[mt][nt][half * 2 + c] + bias[gn];
                    if (EPI == 1) v += res[(size_t)gm * N + gn];
                    if (EPI == 2) Cb[(size_t)gm * N + gn] = __float2bfloat16(gelu_f(v));
                    else if (EPI == 3) Cb[(size_t)gm * N + gn] = __float2bfloat16(v);
                    else Cf[(size_t)gm * N + gn] = v;
                }
            }
        }
    }
}

// ---------------- deformable sampling: 4 heads per warp, uint2 gathers --------
__global__ void sample_kernel(const float* __restrict__ oa,
                              const float* __restrict__ refp,
                              const __nv_bfloat16* __restrict__ v,
                              __nv_bfloat16* __restrict__ out)
{
    int gwarp = blockIdx.x * 8 + (threadIdx.x >> 5);
    int bq    = gwarp >> 1;
    int hbase = (gwarp & 1) * 4;
    int lane  = threadIdx.x & 31;
    int g     = lane >> 3;
    int h     = hbase + g;
    int c4    = (lane & 7) * 4;

    const float* lg = oa + (size_t)bq * NOA + 192 + h * 12;
    float w[12];
    float mx = -1e30f;
    #pragma unroll
    for (int i = 0; i < 12; i++) { w[i] = lg[i]; mx = fmaxf(mx, w[i]); }
    float s = 0.f;
    #pragma unroll
    for (int i = 0; i < 12; i++) { w[i] = __expf(w[i] - mx); s += w[i]; }
    float inv = 1.f / s;

    float rx = refp[(size_t)bq * 2 + 0];
    float ry = refp[(size_t)bq * 2 + 1];

    const float* offp = oa + (size_t)bq * NOA + h * 24;
    int b = bq >> 14;
    const __nv_bfloat16* vb = v + ((size_t)b * NV) * CH + h * DHEAD + c4;

    const int HsA[3]    = {100, 50, 25};
    const int startA[3] = {0, 10000, 12500};

    float a0 = 0.f, a1 = 0.f, a2 = 0.f, a3 = 0.f;
    #pragma unroll
    for (int l = 0; l < 3; l++) {
        const int Wl = HsA[l];
        const float fW = (float)Wl;
        const __nv_bfloat16* vl = vb + (size_t)startA[l] * CH;
        #pragma unroll
        for (int p = 0; p < 4; p++) {
            float ox = offp[(l * 4 + p) * 2 + 0];
            float oy = offp[(l * 4 + p) * 2 + 1];
            float x = (rx + ox / fW) * fW - 0.5f;
            float y = (ry + oy / fW) * fW - 0.5f;
            float x0f = floorf(x), y0f = floorf(y);
            float lx = x - x0f, ly = y - y0f;
            int x0 = (int)x0f, y0 = (int)y0f;

            float mx0 = (x0 >= 0     && x0 < Wl)     ? 1.f : 0.f;
            float mx1 = (x0 + 1 >= 0 && x0 + 1 < Wl) ? 1.f : 0.f;
            float my0 = (y0 >= 0     && y0 < Wl)     ? 1.f : 0.f;
            float my1 = (y0 + 1 >= 0 && y0 + 1 < Wl) ? 1.f : 0.f;

            int xc0 = min(max(x0, 0), Wl - 1);
            int xc1 = min(max(x0 + 1, 0), Wl - 1);
            int yc0 = min(max(y0, 0), Wl - 1);
            int yc1 = min(max(y0 + 1, 0), Wl - 1);

            uint2 q00 = __ldg((const uint2*)(vl + (size_t)(yc0 * Wl + xc0) * CH));
            uint2 q01 = __ldg((const uint2*)(vl + (size_t)(yc0 * Wl + xc1) * CH));
            uint2 q10 = __ldg((const uint2*)(vl + (size_t)(yc1 * Wl + xc0) * CH));
            uint2 q11 = __ldg((const uint2*)(vl + (size_t)(yc1 * Wl + xc1) * CH));

            float wp  = w[l * 4 + p] * inv;
            float w00 = (1.f - lx) * (1.f - ly) * mx0 * my0 * wp;
            float w01 = lx * (1.f - ly) * mx1 * my0 * wp;
            float w10 = (1.f - lx) * ly * mx0 * my1 * wp;
            float w11 = lx * ly * mx1 * my1 * wp;

            float2 f;
            f = __bfloat1622float2(*(__nv_bfloat162*)&q00.x); a0 += f.x * w00; a1 += f.y * w00;
            f = __bfloat1622float2(*(__nv_bfloat162*)&q00.y); a2 += f.x * w00; a3 += f.y * w00;
            f = __bfloat1622float2(*(__nv_bfloat162*)&q01.x); a0 += f.x * w01; a1 += f.y * w01;
            f = __bfloat1622float2(*(__nv_bfloat162*)&q01.y); a2 += f.x * w01; a3 += f.y * w01;
            f = __bfloat1622float2(*(__nv_bfloat162*)&q10.x); a0 += f.x * w10; a1 += f.y * w10;
            f = __bfloat1622float2(*(__nv_bfloat162*)&q10.y); a2 += f.x * w10; a3 += f.y * w10;
            f = __bfloat1622float2(*(__nv_bfloat162*)&q11.x); a0 += f.x * w11; a1 += f.y * w11;
            f = __bfloat1622float2(*(__nv_bfloat162*)&q11.y); a2 += f.x * w11; a3 += f.y * w11;
        }
    }

    __nv_bfloat162 o0 = {__float2bfloat16(a0), __float2bfloat16(a1)};
    __nv_bfloat162 o1 = {__float2bfloat16(a2), __float2bfloat16(a3)};
    *(uint2*)(out + (size_t)bq * CH + h * DHEAD + c4) =
        make_uint2(*(uint32_t*)&o0, *(uint32_t*)&o1);
}

// ---------------- launcher ----------------
extern "C" void kernel_launch(void* const* d_in, const int* in_sizes, int n_in,
                              void* d_out, int out_size)
{
    const float* query = (const float*)d_in[0];
    const float* value = (const float*)d_in[1];
    const float* qpos  = (const float*)d_in[2];
    const float* refp  = (const float*)d_in[3];
    const float* ln1g = (const float*)d_in[6];
    const float* ln1b = (const float*)d_in[7];
    const float* ln2g = (const float*)d_in[8];
    const float* ln2b = (const float*)d_in[9];
    const float* Wv   = (const float*)d_in[10];
    const float* bv   = (const float*)d_in[11];
    const float* Woff = (const float*)d_in[12];
    const float* boff = (const float*)d_in[13];
    const float* Wat  = (const float*)d_in[14];
    const float* bat  = (const float*)d_in[15];
    const float* Wo   = (const float*)d_in[16];
    const float* bo   = (const float*)d_in[17];
    const float* W1   = (const float*)d_in[18];
    const float* b1   = (const float*)d_in[19];
    const float* W2   = (const float*)d_in[20];
    const float* b2   = (const float*)d_in[21];
    float* out = (float*)d_out;

    __nv_bfloat16 *qb, *vbf, *vp, *sampb, *hb, *hidb;
    __nv_bfloat16 *WvT, *WoaT, *WoT, *W1T, *W2T;
    float *oa, *x, *boa;
    cudaGetSymbolAddress((void**)&qb,    g_qb);
    cudaGetSymbolAddress((void**)&vbf,   g_vb);
    cudaGetSymbolAddress((void**)&vp,    g_vp);
    cudaGetSymbolAddress((void**)&oa,    g_oa);
    cudaGetSymbolAddress((void**)&sampb, g_sampb);
    cudaGetSymbolAddress((void**)&x,     g_x);
    cudaGetSymbolAddress((void**)&hb,    g_hb);
    cudaGetSymbolAddress((void**)&hidb,  g_hidb);
    cudaGetSymbolAddress((void**)&WvT,   g_WvT);
    cudaGetSymbolAddress((void**)&WoaT,  g_WoaT);
    cudaGetSymbolAddress((void**)&WoT,   g_WoT);
    cudaGetSymbolAddress((void**)&W1T,   g_W1T);
    cudaGetSymbolAddress((void**)&W2T,   g_W2T);
    cudaGetSymbolAddress((void**)&boa,   g_boa);

    static int attr_done = 0;
    if (!attr_done) {
        cudaFuncSetAttribute(hgemm_kernel<0>, cudaFuncAttributeMaxDynamicSharedMemorySize, GSMEM);
        cudaFuncSetAttribute(hgemm_kernel<1>, cudaFuncAttributeMaxDynamicSharedMemorySize, GSMEM);
        cudaFuncSetAttribute(hgemm_kernel<2>, cudaFuncAttributeMaxDynamicSharedMemorySize, GSMEM);
        cudaFuncSetAttribute(hgemm_kernel<3>, cudaFuncAttributeMaxDynamicSharedMemorySize, GSMEM);
        attr_done = 1;
    }

    auto ggrid = [](int M, int N) { return dim3((N + 127) / 128, (M + 127) / 128); };

    wconv_all<<<(WCONV_TOTAL + 255) / 256, 256>>>(Wv, Woff, Wat, Wo, W1, W2, boff, bat);
    f2b_kernel<<<(MV * CH + 255) / 256, 256>>>(value, vbf, MV * CH);
    ln_kernel<<<MQ / 8, 256>>>(query, ln1g, ln1b, qpos, qb);
    hgemm_kernel<3><<<ggrid(MV, CH), 256, GSMEM>>>(vbf, WvT, bv, nullptr, nullptr, vp, MV, CH, CH);
    hgemm_kernel<0><<<ggrid(MQ, NOA), 256, GSMEM>>>(qb, WoaT, boa, nullptr, oa, nullptr, MQ, NOA, CH);
    sample_kernel<<<MQ / 4, 256>>>(oa, refp, vp, sampb);
    hgemm_kernel<1><<<ggrid(MQ, CH), 256, GSMEM>>>(sampb, WoT, bo, query, x, nullptr, MQ, CH, CH);
    ln_kernel<<<MQ / 8, 256>>>(x, ln2g, ln2b, nullptr, hb);
    hgemm_kernel<2><<<ggrid(MQ, FFN), 256, GSMEM>>>(hb, W1T, b1, nullptr, nullptr, hidb, MQ, FFN, CH);
    hgemm_kernel<1><<<ggrid(MQ, CH), 256, GSMEM>>>(hidb, W2T, b2, x, out, nullptr, MQ, CH, FFN);
}

// round 14
// speedup vs baseline: 7.5624x; 1.3385x over previous
#include <cuda_runtime.h>
#include <cuda_bf16.h>
#include <math.h>
#include <stdint.h>

// ---------------- problem constants ----------------
#define BATCH 2
#define QLEN  16384
#define CH    256
#define HEADS 8
#define DHEAD 32
#define NV    13125          // 100*100 + 50*50 + 25*25
#define NOA   288            // 192 offsets + 96 attn logits
#define FFN   1024
#define MQ    (BATCH*QLEN)   // 32768
#define MV    (BATCH*NV)     // 26250

// ---------------- scratch (allocation-free) ----------------
__device__ __nv_bfloat16 g_qb  [MQ*CH];
__device__ __nv_bfloat16 g_vb  [MV*CH];
__device__ __nv_bfloat16 g_vp  [MV*CH];
__device__ float         g_oa  [MQ*NOA];
__device__ __nv_bfloat16 g_sampb[MQ*CH];
__device__ float         g_x   [MQ*CH];
__device__ __nv_bfloat16 g_hb  [MQ*CH];
__device__ __nv_bfloat16 g_hidb[MQ*FFN];

__device__ __nv_bfloat16 g_WvT [CH*CH];
__device__ __nv_bfloat16 g_WoaT[NOA*CH];
__device__ __nv_bfloat16 g_WoT [CH*CH];
__device__ __nv_bfloat16 g_W1T [FFN*CH];
__device__ __nv_bfloat16 g_W2T [CH*FFN];
__device__ float         g_boa [NOA];

// ---------------- helpers ----------------
__device__ __forceinline__ float gelu_f(float x) {
    // tanh-form GELU with HW tanh.approx: |err vs exact erf-GELU| <~3e-4 abs
    float u = x * (0.7978845608f + 0.0356774081f * x * x);
    float t;
    asm("tanh.approx.f32 %0, %1;" : "=f"(t) : "f"(u));
    return 0.5f * x * (1.0f + t);
}
__device__ __forceinline__ void cp_async16(uint32_t dst, const void* src, int sz) {
    asm volatile("cp.async.cg.shared.global [%0], [%1], 16, %2;\n"
                 :: "r"(dst), "l"(src), "r"(sz));
}
__device__ __forceinline__ void cp_commit() { asm volatile("cp.async.commit_group;\n"); }
__device__ __forceinline__ void ldsm_x4(uint32_t& r0, uint32_t& r1, uint32_t& r2, uint32_t& r3,
                                        uint32_t addr) {
    asm volatile("ldmatrix.sync.aligned.m8n8.x4.shared.b16 {%0,%1,%2,%3}, [%4];\n"
                 : "=r"(r0), "=r"(r1), "=r"(r2), "=r"(r3) : "r"(addr));
}
__device__ __forceinline__ void mma_bf16(float* c, uint32_t a0, uint32_t a1, uint32_t a2,
                                         uint32_t a3, uint32_t b0, uint32_t b1) {
    asm volatile("mma.sync.aligned.m16n8k16.row.col.f32.bf16.bf16.f32 "
                 "{%0,%1,%2,%3}, {%4,%5,%6,%7}, {%8,%9}, {%0,%1,%2,%3};\n"
                 : "+f"(c[0]), "+f"(c[1]), "+f"(c[2]), "+f"(c[3])
                 : "r"(a0), "r"(a1), "r"(a2), "r"(a3), "r"(b0), "r"(b1));
}
#define SWZ128(o) ((o) ^ (((o) >> 3) & 0x70))

// ---------------- all weight transposes + concat in ONE kernel ----------------
__global__ void wconv_all(const float* __restrict__ Wv, const float* __restrict__ Woff,
                          const float* __restrict__ Wat, const float* __restrict__ Wo,
                          const float* __restrict__ W1, const float* __restrict__ W2,
                          const float* __restrict__ boff, const float* __restrict__ bat)
{
    int idx = blockIdx.x * 256 + threadIdx.x;
    if (idx < 65536) {
        int n = idx >> 8, k = idx & 255;
        g_WvT[idx] = __float2bfloat16(Wv[k * CH + n]);
        return;
    }
    idx -= 65536;
    if (idx < 73728) {
        int n = idx >> 8, k = idx & 255;
        float w = (n < 192) ? Woff[k * 192 + n] : Wat[k * 96 + (n - 192)];
        g_WoaT[idx] = __float2bfloat16(w);
        return;
    }
    idx -= 73728;
    if (idx < 65536) {
        int n = idx >> 8, k = idx & 255;
        g_WoT[idx] = __float2bfloat16(Wo[k * CH + n]);
        return;
    }
    idx -= 65536;
    if (idx < 262144) {
        int n = idx >> 8, k = idx & 255;
        g_W1T[idx] = __float2bfloat16(W1[k * FFN + n]);
        return;
    }
    idx -= 262144;
    if (idx < 262144) {
        int n = idx >> 10, k = idx & 1023;
        g_W2T[idx] = __float2bfloat16(W2[k * CH + n]);
        return;
    }
    idx -= 262144;
    if (idx < NOA) g_boa[idx] = (idx < 192) ? boff[idx] : bat[idx - 192];
}
#define WCONV_TOTAL (65536 + 73728 + 65536 + 262144 + 262144 + NOA)

// ---------------- fp32 -> bf16, float4 vectorized ----------------
__global__ void f2b4_kernel(const float4* __restrict__ in, uint2* __restrict__ out, int n4) {
    int idx = blockIdx.x * 256 + threadIdx.x;
    if (idx >= n4) return;
    float4 v = in[idx];
    __nv_bfloat162 p0 = {__float2bfloat16(v.x), __float2bfloat16(v.y)};
    __nv_bfloat162 p1 = {__float2bfloat16(v.z), __float2bfloat16(v.w)};
    out[idx] = make_uint2(*(uint32_t*)&p0, *(uint32_t*)&p1);
}

// ---------------- LayerNorm -> bf16 : one warp per row, shuffle reduce --------
__global__ void ln_kernel(const float* __restrict__ x,
                          const float* __restrict__ g,
                          const float* __restrict__ b,
                          const float* __restrict__ add,
                          __nv_bfloat16* __restrict__ out)
{
    int warp = threadIdx.x >> 5;
    int lane = threadIdx.x & 31;
    int row  = blockIdx.x * 8 + warp;

    const float4* xr = (const float4*)(x + (size_t)row * CH);
    float4 v0 = xr[lane];
    float4 v1 = xr[lane + 32];

    float s = v0.x + v0.y + v0.z + v0.w + v1.x + v1.y + v1.z + v1.w;
    #pragma unroll
    for (int o = 16; o > 0; o >>= 1) s += __shfl_xor_sync(0xffffffffu, s, o);
    float mean = s * (1.0f / CH);

    float d0x = v0.x - mean, d0y = v0.y - mean, d0z = v0.z - mean, d0w = v0.w - mean;
    float d1x = v1.x - mean, d1y = v1.y - mean, d1z = v1.z - mean, d1w = v1.w - mean;
    float q = d0x*d0x + d0y*d0y + d0z*d0z + d0w*d0w + d1x*d1x + d1y*d1y + d1z*d1z + d1w*d1w;
    #pragma unroll
    for (int o = 16; o > 0; o >>= 1) q += __shfl_xor_sync(0xffffffffu, q, o);
    float rstd = rsqrtf(q * (1.0f / CH) + 1e-5f);

    const float4* gp = (const float4*)g;
    const float4* bp = (const float4*)b;
    float4 g0 = gp[lane], g1 = gp[lane + 32];
    float4 b0 = bp[lane], b1 = bp[lane + 32];

    float y0x = d0x * rstd * g0.x + b0.x;
    float y0y = d0y * rstd * g0.y + b0.y;
    float y0z = d0z * rstd * g0.z + b0.z;
    float y0w = d0w * rstd * g0.w + b0.w;
    float y1x = d1x * rstd * g1.x + b1.x;
    float y1y = d1y * rstd * g1.y + b1.y;
    float y1z = d1z * rstd * g1.z + b1.z;
    float y1w = d1w * rstd * g1.w + b1.w;

    if (add) {
        const float4* ar = (const float4*)(add + (size_t)row * CH);
        float4 a0 = ar[lane], a1 = ar[lane + 32];
        y0x += a0.x; y0y += a0.y; y0z += a0.z; y0w += a0.w;
        y1x += a1.x; y1y += a1.y; y1z += a1.z; y1w += a1.w;
    }

    __nv_bfloat16* orow = out + (size_t)row * CH;
    __nv_bfloat162 p0 = {__float2bfloat16(y0x), __float2bfloat16(y0y)};
    __nv_bfloat162 p1 = {__float2bfloat16(y0z), __float2bfloat16(y0w)};
    __nv_bfloat162 p2 = {__float2bfloat16(y1x), __float2bfloat16(y1y)};
    __nv_bfloat162 p3 = {__float2bfloat16(y1z), __float2bfloat16(y1w)};
    ((uint2*)orow)[lane]      = make_uint2(*(uint32_t*)&p0, *(uint32_t*)&p1);
    ((uint2*)orow)[lane + 32] = make_uint2(*(uint32_t*)&p2, *(uint32_t*)&p3);
}

// ---------------- bf16 HMMA GEMM 128x128, K-chunks of 64, canonical SW128 -----
// EPI 0: fp32=acc+bias ; 1: fp32=acc+bias+res ; 2: bf16=gelu(acc+bias) ; 3: bf16=acc+bias
#define KC        64
#define TILE_B    16384
#define STAGE_B   (2 * TILE_B)
#define STAGES    3
#define GSMEM     (STAGES * STAGE_B)      // 98304 bytes

template<int EPI>
__global__ void __launch_bounds__(256, 2)
hgemm_kernel(const __nv_bfloat16* __restrict__ A,
             const __nv_bfloat16* __restrict__ Bt,
             const float* __restrict__ bias,
             const float* __restrict__ res,
             float* __restrict__ Cf,
             __nv_bfloat16* __restrict__ Cb,
             int M, int N, int K)
{
    extern __shared__ char dsmem[];
    const uint32_t sb = (uint32_t)__cvta_generic_to_shared(dsmem);

    const int tid  = threadIdx.x;
    const int lane = tid & 31;
    const int warp = tid >> 5;
    const int wm   = warp >> 2;
    const int wn   = warp & 3;
    const int bm   = blockIdx.y * 128;
    const int bn   = blockIdx.x * 128;

    float acc[4][4][4];
    #pragma unroll
    for (int i = 0; i < 4; i++)
        #pragma unroll
        for (int j = 0; j < 4; j++)
            #pragma unroll
            for (int r = 0; r < 4; r++) acc[i][j][r] = 0.f;

    const int KT = K >> 6;

    auto issue = [&](int kt, int st) {
        const uint32_t dA = sb + (uint32_t)st * STAGE_B;
        const uint32_t dB = dA + TILE_B;
        const int kc = kt * KC;
        #pragma unroll
        for (int i = 0; i < 4; i++) {
            int slot = tid + i * 256;
            int row  = slot >> 3;
            int colb = (slot & 7) * 16;
            uint32_t so = SWZ128((uint32_t)(row * 128 + colb));
            int gm = bm + row;
            cp_async16(dA + so, A + (size_t)(gm < M ? gm : M - 1) * K + kc + (colb >> 1),
                       gm < M ? 16 : 0);
            int gn = bn + row;
            cp_async16(dB + so, Bt + (size_t)(gn < N ? gn : N - 1) * K + kc + (colb >> 1),
                       gn < N ? 16 : 0);
        }
        cp_commit();
    };

    issue(0, 0);
    if (KT > 1) issue(1, 1);

    int buf = 0;
    int nxt = (KT > 2) ? 2 : 0;

    for (int kt = 0; kt < KT; kt++) {
        if (kt + 1 < KT) asm volatile("cp.async.wait_group 1;\n");
        else             asm volatile("cp.async.wait_group 0;\n");
        __syncthreads();

        if (kt + 2 < KT) issue(kt + 2, nxt);

        const uint32_t aB = sb + (uint32_t)buf * STAGE_B;
        const uint32_t bB = aB + TILE_B;

        #pragma unroll
        for (int ks = 0; ks < 4; ks++) {
            uint32_t a[4][4];
            #pragma unroll
            for (int mt = 0; mt < 4; mt++) {
                int row  = wm * 64 + mt * 16 + (lane & 15);
                int colb = ks * 32 + (lane >> 4) * 16;
                ldsm_x4(a[mt][0], a[mt][1], a[mt][2], a[mt][3],
                        aB + SWZ128((uint32_t)(row * 128 + colb)));
            }
            uint32_t b[4][2];
            #pragma unroll
            for (int np = 0; np < 2; np++) {
                int g    = lane >> 3;
                int row  = wn * 32 + np * 16 + (g >> 1) * 8 + (lane & 7);
                int colb = ks * 32 + (g & 1) * 16;
                uint32_t r0, r1, r2, r3;
                ldsm_x4(r0, r1, r2, r3, bB + SWZ128((uint32_t)(row * 128 + colb)));
                b[np * 2 + 0][0] = r0; b[np * 2 + 0][1] = r1;
                b[np * 2 + 1][0] = r2; b[np * 2 + 1][1] = r3;
            }
            #pragma unroll
            for (int mt = 0; mt < 4; mt++)
                #pragma unroll
                for (int nt = 0; nt < 4; nt++)
                    mma_bf16(acc[mt][nt], a[mt][0], a[mt][1], a[mt][2], a[mt][3],
                             b[nt][0], b[nt][1]);
        }

        buf = (buf + 1 == STAGES) ? 0 : buf + 1;
        nxt = (nxt + 1 == STAGES) ? 0 : nxt + 1;
    }

    // vectorized epilogue: 2-wide stores, float2 bias/residual
    #pragma unroll
    for (int nt = 0; nt < 4; nt++) {
        int n0 = bn + wn * 32 + nt * 8 + (lane & 3) * 2;
        if (n0 >= N) continue;
        float2 bi = *(const float2*)(bias + n0);
        #pragma unroll
        for (int mt = 0; mt < 4; mt++) {
            #pragma unroll
            for (int half = 0; half < 2; half++) {
                int gm = bm + wm * 64 + mt * 16 + (lane >> 2) + half * 8;
                if (gm >= M) continue;
                float v0 = acc[mt][nt][half * 2 + 0] + bi.x;
                float v1 = acc[mt][nt][half * 2 + 1] + bi.y;
                if (EPI == 1) {
                    float2 rr = *(const float2*)(res + (size_t)gm * N + n0);
                    v0 += rr.x; v1 += rr.y;
                }
                if (EPI == 2) {
                    __nv_bfloat162 h = {__float2bfloat16(gelu_f(v0)), __float2bfloat16(gelu_f(v1))};
                    *(__nv_bfloat162*)(Cb + (size_t)gm * N + n0) = h;
                } else if (EPI == 3) {
                    __nv_bfloat162 h = {__float2bfloat16(v0), __float2bfloat16(v1)};
                    *(__nv_bfloat162*)(Cb + (size_t)gm * N + n0) = h;
                } else {
                    *(float2*)(Cf + (size_t)gm * N + n0) = make_float2(v0, v1);
                }
            }
        }
    }
}

// ---------------- deformable sampling: 4 heads per warp, uint2 gathers --------
__global__ void sample_kernel(const float* __restrict__ oa,
                              const float* __restrict__ refp,
                              const __nv_bfloat16* __restrict__ v,
                              __nv_bfloat16* __restrict__ out)
{
    int gwarp = blockIdx.x * 8 + (threadIdx.x >> 5);
    int bq    = gwarp >> 1;
    int hbase = (gwarp & 1) * 4;
    int lane  = threadIdx.x & 31;
    int g     = lane >> 3;
    int h     = hbase + g;
    int c4    = (lane & 7) * 4;

    const float* lg = oa + (size_t)bq * NOA + 192 + h * 12;
    float w[12];
    float mx = -1e30f;
    #pragma unroll
    for (int i = 0; i < 12; i++) { w[i] = lg[i]; mx = fmaxf(mx, w[i]); }
    float s = 0.f;
    #pragma unroll
    for (int i = 0; i < 12; i++) { w[i] = __expf(w[i] - mx); s += w[i]; }
    float inv = 1.f / s;

    float rx = refp[(size_t)bq * 2 + 0];
    float ry = refp[(size_t)bq * 2 + 1];

    const float* offp = oa + (size_t)bq * NOA + h * 24;
    int b = bq >> 14;
    const __nv_bfloat16* vb = v + ((size_t)b * NV) * CH + h * DHEAD + c4;

    const int HsA[3]    = {100, 50, 25};
    const int startA[3] = {0, 10000, 12500};

    float a0 = 0.f, a1 = 0.f, a2 = 0.f, a3 = 0.f;
    #pragma unroll
    for (int l = 0; l < 3; l++) {
        const int Wl = HsA[l];
        const float fW = (float)Wl;
        const __nv_bfloat16* vl = vb + (size_t)startA[l] * CH;
        #pragma unroll
        for (int p = 0; p < 4; p++) {
            float ox = offp[(l * 4 + p) * 2 + 0];
            float oy = offp[(l * 4 + p) * 2 + 1];
            float x = (rx + ox / fW) * fW - 0.5f;
            float y = (ry + oy / fW) * fW - 0.5f;
            float x0f = floorf(x), y0f = floorf(y);
            float lx = x - x0f, ly = y - y0f;
            int x0 = (int)x0f, y0 = (int)y0f;

            float mx0 = (x0 >= 0     && x0 < Wl)     ? 1.f : 0.f;
            float mx1 = (x0 + 1 >= 0 && x0 + 1 < Wl) ? 1.f : 0.f;
            float my0 = (y0 >= 0     && y0 < Wl)     ? 1.f : 0.f;
            float my1 = (y0 + 1 >= 0 && y0 + 1 < Wl) ? 1.f : 0.f;

            int xc0 = min(max(x0, 0), Wl - 1);
            int xc1 = min(max(x0 + 1, 0), Wl - 1);
            int yc0 = min(max(y0, 0), Wl - 1);
            int yc1 = min(max(y0 + 1, 0), Wl - 1);

            uint2 q00 = __ldg((const uint2*)(vl + (size_t)(yc0 * Wl + xc0) * CH));
            uint2 q01 = __ldg((const uint2*)(vl + (size_t)(yc0 * Wl + xc1) * CH));
            uint2 q10 = __ldg((const uint2*)(vl + (size_t)(yc1 * Wl + xc0) * CH));
            uint2 q11 = __ldg((const uint2*)(vl + (size_t)(yc1 * Wl + xc1) * CH));

            float wp  = w[l * 4 + p] * inv;
            float w00 = (1.f - lx) * (1.f - ly) * mx0 * my0 * wp;
            float w01 = lx * (1.f - ly) * mx1 * my0 * wp;
            float w10 = (1.f - lx) * ly * mx0 * my1 * wp;
            float w11 = lx * ly * mx1 * my1 * wp;

            float2 f;
            f = __bfloat1622float2(*(__nv_bfloat162*)&q00.x); a0 += f.x * w00; a1 += f.y * w00;
            f = __bfloat1622float2(*(__nv_bfloat162*)&q00.y); a2 += f.x * w00; a3 += f.y * w00;
            f = __bfloat1622float2(*(__nv_bfloat162*)&q01.x); a0 += f.x * w01; a1 += f.y * w01;
            f = __bfloat1622float2(*(__nv_bfloat162*)&q01.y); a2 += f.x * w01; a3 += f.y * w01;
            f = __bfloat1622float2(*(__nv_bfloat162*)&q10.x); a0 += f.x * w10; a1 += f.y * w10;
            f = __bfloat1622float2(*(__nv_bfloat162*)&q10.y); a2 += f.x * w10; a3 += f.y * w10;
            f = __bfloat1622float2(*(__nv_bfloat162*)&q11.x); a0 += f.x * w11; a1 += f.y * w11;
            f = __bfloat1622float2(*(__nv_bfloat162*)&q11.y); a2 += f.x * w11; a3 += f.y * w11;
        }
    }

    __nv_bfloat162 o0 = {__float2bfloat16(a0), __float2bfloat16(a1)};
    __nv_bfloat162 o1 = {__float2bfloat16(a2), __float2bfloat16(a3)};
    *(uint2*)(out + (size_t)bq * CH + h * DHEAD + c4) =
        make_uint2(*(uint32_t*)&o0, *(uint32_t*)&o1);
}

// ---------------- launcher with forked capture-graph branches ----------------
extern "C" void kernel_launch(void* const* d_in, const int* in_sizes, int n_in,
                              void* d_out, int out_size)
{
    const float* query = (const float*)d_in[0];
    const float* value = (const float*)d_in[1];
    const float* qpos  = (const float*)d_in[2];
    const float* refp  = (const float*)d_in[3];
    const float* ln1g = (const float*)d_in[6];
    const float* ln1b = (const float*)d_in[7];
    const float* ln2g = (const float*)d_in[8];
    const float* ln2b = (const float*)d_in[9];
    const float* Wv   = (const float*)d_in[10];
    const float* bv   = (const float*)d_in[11];
    const float* Woff = (const float*)d_in[12];
    const float* boff = (const float*)d_in[13];
    const float* Wat  = (const float*)d_in[14];
    const float* bat  = (const float*)d_in[15];
    const float* Wo   = (const float*)d_in[16];
    const float* bo   = (const float*)d_in[17];
    const float* W1   = (const float*)d_in[18];
    const float* b1   = (const float*)d_in[19];
    const float* W2   = (const float*)d_in[20];
    const float* b2   = (const float*)d_in[21];
    float* out = (float*)d_out;

    __nv_bfloat16 *qb, *vbf, *vp, *sampb, *hb, *hidb;
    __nv_bfloat16 *WvT, *WoaT, *WoT, *W1T, *W2T;
    float *oa, *x, *boa;
    cudaGetSymbolAddress((void**)&qb,    g_qb);
    cudaGetSymbolAddress((void**)&vbf,   g_vb);
    cudaGetSymbolAddress((void**)&vp,    g_vp);
    cudaGetSymbolAddress((void**)&oa,    g_oa);
    cudaGetSymbolAddress((void**)&sampb, g_sampb);
    cudaGetSymbolAddress((void**)&x,     g_x);
    cudaGetSymbolAddress((void**)&hb,    g_hb);
    cudaGetSymbolAddress((void**)&hidb,  g_hidb);
    cudaGetSymbolAddress((void**)&WvT,   g_WvT);
    cudaGetSymbolAddress((void**)&WoaT,  g_WoaT);
    cudaGetSymbolAddress((void**)&WoT,   g_WoT);
    cudaGetSymbolAddress((void**)&W1T,   g_W1T);
    cudaGetSymbolAddress((void**)&W2T,   g_W2T);
    cudaGetSymbolAddress((void**)&boa,   g_boa);

    static cudaStream_t s2 = nullptr;
    static cudaEvent_t eFork = nullptr, eW = nullptr, eV = nullptr;
    if (!s2) {
        cudaStreamCreateWithFlags(&s2, cudaStreamNonBlocking);
        cudaEventCreateWithFlags(&eFork, cudaEventDisableTiming);
        cudaEventCreateWithFlags(&eW,    cudaEventDisableTiming);
        cudaEventCreateWithFlags(&eV,    cudaEventDisableTiming);
        cudaFuncSetAttribute(hgemm_kernel<0>, cudaFuncAttributeMaxDynamicSharedMemorySize, GSMEM);
        cudaFuncSetAttribute(hgemm_kernel<1>, cudaFuncAttributeMaxDynamicSharedMemorySize, GSMEM);
        cudaFuncSetAttribute(hgemm_kernel<2>, cudaFuncAttributeMaxDynamicSharedMemorySize, GSMEM);
        cudaFuncSetAttribute(hgemm_kernel<3>, cudaFuncAttributeMaxDynamicSharedMemorySize, GSMEM);
    }

    auto ggrid = [](int M, int N) { return dim3((N + 127) / 128, (M + 127) / 128); };

    // fork: branch s2 = wconv -> f2b -> vproj ; main = ln1 -> oa
    cudaEventRecord(eFork, 0);
    cudaStreamWaitEvent(s2, eFork, 0);

    wconv_all<<<(WCONV_TOTAL + 255) / 256, 256, 0, s2>>>(Wv, Woff, Wat, Wo, W1, W2, boff, bat);
    cudaEventRecord(eW, s2);                     // weights ready (oa needs WoaT)
    f2b4_kernel<<<(MV * CH / 4 + 255) / 256, 256, 0, s2>>>((const float4*)value, (uint2*)vbf,
                                                           MV * CH / 4);
    hgemm_kernel<3><<<ggrid(MV, CH), 256, GSMEM, s2>>>(vbf, WvT, bv, nullptr, nullptr, vp,
                                                       MV, CH, CH);
    cudaEventRecord(eV, s2);                     // vp ready

    ln_kernel<<<MQ / 8, 256>>>(query, ln1g, ln1b, qpos, qb);
    cudaStreamWaitEvent(0, eW, 0);
    hgemm_kernel<0><<<ggrid(MQ, NOA), 256, GSMEM>>>(qb, WoaT, boa, nullptr, oa, nullptr,
                                                    MQ, NOA, CH);
    cudaStreamWaitEvent(0, eV, 0);               // join vproj branch
    sample_kernel<<<MQ / 4, 256>>>(oa, refp, vp, sampb);
    hgemm_kernel<1><<<ggrid(MQ, CH), 256, GSMEM>>>(sampb, WoT, bo, query, x, nullptr, MQ, CH, CH);
    ln_kernel<<<MQ / 8, 256>>>(x, ln2g, ln2b, nullptr, hb);
    hgemm_kernel<2><<<ggrid(MQ, FFN), 256, GSMEM>>>(hb, W1T, b1, nullptr, nullptr, hidb,
                                                    MQ, FFN, CH);
    hgemm_kernel<1><<<ggrid(MQ, CH), 256, GSMEM>>>(hidb, W2T, b2, x, out, nullptr, MQ, CH, FFN);
}